// round 5
// baseline (speedup 1.0000x reference)
#include <cuda_runtime.h>
#include <math.h>

#define BB 128
#define TT 2048
#define HH 200
#define STEPS 5

// scores GEMM tiling
#define BM 64      // t-rows per block
#define BK 20      // k-chunk
#define TM 8
#define TN 8
#define NTHR 200   // 25 tx (h) * 8 ty (t)

__device__ float d_qpb[BB*HH];     // q@Wa.T + ba + bua
__device__ float d_UaT[HH*HH];     // UaT[k*H+h] = Ua[h*H+k]
__device__ float d_scores[BB*TT];
__device__ float d_attn[BB*TT];
__device__ float d_ctx[BB*HH];

__device__ __forceinline__ float fast_tanh(float x){
    float e = __expf(2.0f*x);            // ex2-based, ~2ulp
    return 1.0f - 2.0f/(e+1.0f);         // exact saturation at +-1
}
__device__ __forceinline__ float sigm(float x){
    return 1.0f/(1.0f+__expf(-x));
}

// ---------------------------------------------------------------- K0: Ua^T
__global__ void transpose_ua(const float* __restrict__ Ua){
    int idx = blockIdx.x*blockDim.x + threadIdx.x;
    if (idx < HH*HH){
        int k = idx / HH, h = idx % HH;
        d_UaT[idx] = Ua[h*HH + k];
    }
}

// ------------------------------------------------- K1: qpb = h0@Wa.T+ba+bua
__global__ void qproj_kernel(const float* __restrict__ h0, const float* __restrict__ Wa,
                             const float* __restrict__ ba, const float* __restrict__ bua){
    int b = blockIdx.x;
    __shared__ float qS[HH];
    for (int k = threadIdx.x; k < HH; k += blockDim.x) qS[k] = h0[b*HH + k];
    __syncthreads();
    int h = threadIdx.x;
    if (h < HH){
        const float* w = Wa + h*HH;
        float s = ba[h] + bua[h];
        #pragma unroll 4
        for (int k = 0; k < HH; k++) s += qS[k]*w[k];
        d_qpb[b*HH + h] = s;
    }
}

// -------- K2: scores[b,t] = bva + sum_h Va[h]*tanh(qpb[b,h] + enc[b,t]:·Ua[h]:)
__global__ void __launch_bounds__(NTHR, 2)
scores_kernel(const float* __restrict__ enc, const float* __restrict__ Va,
              const float* __restrict__ bva){
    __shared__ __align__(16) float EncS[BK][BM+4];   // [dk][t], pad for banks
    __shared__ __align__(16) float UaS[BK][HH];      // [dk][h]
    __shared__ float qbS[HH];
    __shared__ float VaS[HH];
    __shared__ float red[BM][25];

    int b  = blockIdx.y;
    int t0 = blockIdx.x * BM;
    int tid = threadIdx.x;
    int tx = tid % 25;    // h-group: h = tx*8 + j  (covers 0..199 exactly)
    int ty = tid / 25;    // t-group: t = ty*8 + i

    for (int h = tid; h < HH; h += NTHR){ qbS[h] = d_qpb[b*HH+h]; VaS[h] = Va[h]; }

    float acc[TM][TN];
    #pragma unroll
    for (int i=0;i<TM;i++)
        #pragma unroll
        for (int j=0;j<TN;j++) acc[i][j]=0.f;

    const float* encB = enc + ((size_t)b*TT + t0)*HH;

    for (int k0 = 0; k0 < HH; k0 += BK){
        __syncthreads();
        for (int i = tid; i < BK*BM; i += NTHR){
            int dk = i % BK, t = i / BK;
            EncS[dk][t] = encB[(size_t)t*HH + k0 + dk];
        }
        for (int i = tid; i < BK*HH; i += NTHR){
            int h = i % HH, dk = i / HH;
            UaS[dk][h] = d_UaT[(k0+dk)*HH + h];
        }
        __syncthreads();
        #pragma unroll 5
        for (int dk = 0; dk < BK; dk++){
            float4 a0 = *(const float4*)&EncS[dk][ty*TM];
            float4 a1 = *(const float4*)&EncS[dk][ty*TM+4];
            float4 b0 = *(const float4*)&UaS[dk][tx*TN];
            float4 b1 = *(const float4*)&UaS[dk][tx*TN+4];
            float a[TM]  = {a0.x,a0.y,a0.z,a0.w,a1.x,a1.y,a1.z,a1.w};
            float bb[TN] = {b0.x,b0.y,b0.z,b0.w,b1.x,b1.y,b1.z,b1.w};
            #pragma unroll
            for (int i=0;i<TM;i++)
                #pragma unroll
                for (int j=0;j<TN;j++) acc[i][j] += a[i]*bb[j];
        }
    }

    // epilogue: tanh + Va reduction over this thread's 8 h values
    float s[TM];
    #pragma unroll
    for (int i=0;i<TM;i++) s[i]=0.f;
    #pragma unroll
    for (int j=0;j<TN;j++){
        int h = tx*TN+j;
        float vh = VaS[h], qb = qbS[h];
        #pragma unroll
        for (int i=0;i<TM;i++) s[i] += vh * fast_tanh(qb + acc[i][j]);
    }
    __syncthreads();
    #pragma unroll
    for (int i=0;i<TM;i++) red[ty*TM+i][tx] = s[i];
    __syncthreads();
    if (tid < BM){
        float sum = bva[0];
        #pragma unroll
        for (int xx=0; xx<25; xx++) sum += red[tid][xx];
        d_scores[(size_t)b*TT + t0 + tid] = sum;
    }
}

// ---------------------------------------------------------- K3: softmax over T
__global__ void softmax_kernel(){
    int b = blockIdx.x;
    int tid = threadIdx.x;
    __shared__ float red[256];
    float v[8];
    float m = -1e30f;
    #pragma unroll
    for (int i=0;i<8;i++){ v[i] = d_scores[(size_t)b*TT + tid + i*256]; m = fmaxf(m, v[i]); }
    red[tid] = m; __syncthreads();
    for (int s=128; s>0; s>>=1){ if (tid<s) red[tid]=fmaxf(red[tid],red[tid+s]); __syncthreads(); }
    m = red[0]; __syncthreads();
    float sum=0.f;
    #pragma unroll
    for (int i=0;i<8;i++){ v[i]=__expf(v[i]-m); sum+=v[i]; }
    red[tid]=sum; __syncthreads();
    for (int s=128;s>0;s>>=1){ if(tid<s) red[tid]+=red[tid+s]; __syncthreads(); }
    float inv = 1.0f/red[0];
    #pragma unroll
    for (int i=0;i<8;i++) d_attn[(size_t)b*TT + tid + i*256] = v[i]*inv;
}

// ------------------------------------------- K4: context[b,h] = sum_t attn*enc
__global__ void context_kernel(const float* __restrict__ enc){
    int b = blockIdx.x;
    __shared__ float attnS[TT];
    for (int t = threadIdx.x; t < TT; t += blockDim.x) attnS[t] = d_attn[(size_t)b*TT + t];
    __syncthreads();
    int h = threadIdx.x;
    if (h < HH){
        const float* e = enc + (size_t)b*TT*HH + h;
        float a0=0,a1=0,a2=0,a3=0;
        #pragma unroll 4
        for (int t=0;t<TT;t+=4){
            a0 += attnS[t]   * e[(size_t)t*HH];
            a1 += attnS[t+1] * e[(size_t)(t+1)*HH];
            a2 += attnS[t+2] * e[(size_t)(t+2)*HH];
            a3 += attnS[t+3] * e[(size_t)(t+3)*HH];
        }
        d_ctx[b*HH+h] = (a0+a1)+(a2+a3);
    }
}

// --------- K5: 5 decoder steps. gates = gate_base + x*w0; LSTM cell; 200->100->50->1
__global__ void decoder_kernel(const float* __restrict__ x, const float* __restrict__ h0,
                               const float* __restrict__ c0,
                               const float* __restrict__ W_ih, const float* __restrict__ W_hh,
                               const float* __restrict__ b_ih, const float* __restrict__ b_hh,
                               const float* __restrict__ W1, const float* __restrict__ b1,
                               const float* __restrict__ W2, const float* __restrict__ b2,
                               const float* __restrict__ W3, const float* __restrict__ b3,
                               float* __restrict__ out){
    int b = blockIdx.x;
    int tid = threadIdx.x;
    __shared__ float ctxS[HH], h0S[HH], c0S[HH];
    __shared__ float gb[4*HH], w0[4*HH];
    __shared__ float hbuf[HH], o1[100], o2[50];
    __shared__ float xs;
    for (int k=tid;k<HH;k+=blockDim.x){
        ctxS[k]=d_ctx[b*HH+k]; h0S[k]=h0[b*HH+k]; c0S[k]=c0[b*HH+k];
    }
    if (tid==0) xs = x[b];
    __syncthreads();
    // gate_base = b_ih + b_hh + ctx@W_ih[:,1:].T + h0@W_hh.T   (constant over steps)
    for (int j=tid; j<4*HH; j+=blockDim.x){
        const float* wih = W_ih + (size_t)j*(HH+1);
        const float* whh = W_hh + (size_t)j*HH;
        w0[j] = wih[0];
        float s = b_ih[j] + b_hh[j];
        #pragma unroll 4
        for (int k=0;k<HH;k++) s += ctxS[k]*wih[1+k] + h0S[k]*whh[k];
        gb[j] = s;
    }
    __syncthreads();
    for (int st=0; st<STEPS; st++){
        float xv = xs;
        if (tid < HH){
            float ig = gb[tid]      + xv*w0[tid];
            float fg = gb[HH+tid]   + xv*w0[HH+tid];
            float gg = gb[2*HH+tid] + xv*w0[2*HH+tid];
            float og = gb[3*HH+tid] + xv*w0[3*HH+tid];
            float c  = sigm(fg)*c0S[tid] + sigm(ig)*fast_tanh(gg);
            float hn = sigm(og)*fast_tanh(c);
            hbuf[tid] = fmaxf(hn, 0.0f);
        }
        __syncthreads();
        if (tid < 100){
            const float* w = W1 + tid*HH;
            float s1 = b1[tid];
            #pragma unroll 4
            for (int k=0;k<HH;k++) s1 += w[k]*hbuf[k];
            o1[tid] = fmaxf(s1, 0.0f);
        }
        __syncthreads();
        if (tid < 50){
            const float* w = W2 + tid*100;
            float s2 = b2[tid];
            #pragma unroll 4
            for (int k=0;k<100;k++) s2 += w[k]*o1[k];
            o2[tid] = fmaxf(s2, 0.0f);
        }
        __syncthreads();
        if (tid == 0){
            float y = b3[0];
            #pragma unroll
            for (int k=0;k<50;k++) y += W3[k]*o2[k];
            out[b*STEPS + st] = y;
            xs = y;   // decoded output feeds back as next input
        }
        __syncthreads();
    }
}

extern "C" void kernel_launch(void* const* d_in, const int* in_sizes, int n_in,
                              void* d_out, int out_size){
    const float* x    = (const float*)d_in[0];
    const float* h0   = (const float*)d_in[1];
    const float* c0   = (const float*)d_in[2];
    const float* enc  = (const float*)d_in[3];
    const float* Wa   = (const float*)d_in[4];
    const float* ba   = (const float*)d_in[5];
    const float* Ua   = (const float*)d_in[6];
    const float* bua  = (const float*)d_in[7];
    const float* Va   = (const float*)d_in[8];
    const float* bva  = (const float*)d_in[9];
    const float* W_ih = (const float*)d_in[10];
    const float* W_hh = (const float*)d_in[11];
    const float* b_ih = (const float*)d_in[12];
    const float* b_hh = (const float*)d_in[13];
    const float* W1   = (const float*)d_in[14];
    const float* b1   = (const float*)d_in[15];
    const float* W2   = (const float*)d_in[16];
    const float* b2   = (const float*)d_in[17];
    const float* W3   = (const float*)d_in[18];
    const float* b3   = (const float*)d_in[19];
    float* out = (float*)d_out;

    transpose_ua<<<(HH*HH+255)/256, 256>>>(Ua);
    qproj_kernel<<<BB, 256>>>(h0, Wa, ba, bua);
    dim3 g2(TT/BM, BB);
    scores_kernel<<<g2, NTHR>>>(enc, Va, bva);
    softmax_kernel<<<BB, 256>>>();
    context_kernel<<<BB, 256>>>(enc);
    decoder_kernel<<<BB, 256>>>(x, h0, c0, W_ih, W_hh, b_ih, b_hh, W1, b1, W2, b2, W3, b3, out);
}

// round 8
// speedup vs baseline: 1.6637x; 1.6637x over previous
#include <cuda_runtime.h>
#include <cuda_bf16.h>
#include <cstdint>
#include <math.h>

#define BB 128
#define TT 2048
#define HH 200
#define STEPS 5

// ---------------- mma.sync scores-GEMM geometry ----------------
#define BM      128              // t rows per CTA
#define KC      64               // bf16 k per smem chunk
#define NCHUNK  4                // k 0..255 (200 real + zero pad)
#define NTHR    512              // 16 warps
#define NB      208              // padded n (h) rows in B smem (26 tiles of 8)
#define SROW    144              // smem row stride bytes (72 bf16): conflict-free ldmatrix
// smem offsets
#define OFF_AH  0                // A_hi [128][72] bf16
#define OFF_AL  18432            // A_lo
#define OFF_BH  36864            // B_hi [208][72] bf16
#define OFF_BL  66816            // B_lo
#define OFF_QB  96768            // qpb [200] f32
#define OFF_VA  97568            // Va  [200] f32
#define OFF_RED 98368            // red [128][2] f32
#define SMEM_TOTAL 99392

__device__ float d_qpb[BB*HH];
__device__ float d_scores[BB*TT];
__device__ float d_attn[BB*TT];
__device__ float d_ctx[BB*HH];

__device__ __forceinline__ float fast_tanh(float x){
    float e = __expf(2.0f*x);
    return 1.0f - 2.0f/(e+1.0f);
}
__device__ __forceinline__ float sigm(float x){
    return 1.0f/(1.0f+__expf(-x));
}
__device__ __forceinline__ uint32_t smem_u32(const void* p){
    uint32_t a;
    asm("{ .reg .u64 t; cvta.to.shared.u64 t, %1; cvt.u32.u64 %0, t; }" : "=r"(a) : "l"(p));
    return a;
}
__device__ __forceinline__ void ldsm_x4(uint32_t* r, uint32_t addr){
    asm volatile("ldmatrix.sync.aligned.m8n8.x4.shared.b16 {%0,%1,%2,%3}, [%4];"
        : "=r"(r[0]),"=r"(r[1]),"=r"(r[2]),"=r"(r[3]) : "r"(addr));
}
__device__ __forceinline__ void ldsm_x2(uint32_t* r, uint32_t addr){
    asm volatile("ldmatrix.sync.aligned.m8n8.x2.shared.b16 {%0,%1}, [%2];"
        : "=r"(r[0]),"=r"(r[1]) : "r"(addr));
}
__device__ __forceinline__ void mma_bf16(float* c, const uint32_t* a, const uint32_t* b){
    asm volatile("mma.sync.aligned.m16n8k16.row.col.f32.bf16.bf16.f32 "
        "{%0,%1,%2,%3}, {%4,%5,%6,%7}, {%8,%9}, {%0,%1,%2,%3};"
        : "+f"(c[0]),"+f"(c[1]),"+f"(c[2]),"+f"(c[3])
        : "r"(a[0]),"r"(a[1]),"r"(a[2]),"r"(a[3]), "r"(b[0]),"r"(b[1]));
}
__device__ __forceinline__ void split2(float2 v, uint32_t& hi, uint32_t& lo){
    __nv_bfloat16 h0b = __float2bfloat16_rn(v.x), h1b = __float2bfloat16_rn(v.y);
    __nv_bfloat16 l0b = __float2bfloat16_rn(v.x - __bfloat162float(h0b));
    __nv_bfloat16 l1b = __float2bfloat16_rn(v.y - __bfloat162float(h1b));
    hi = ((uint32_t)__bfloat16_as_ushort(h1b)<<16) | __bfloat16_as_ushort(h0b);
    lo = ((uint32_t)__bfloat16_as_ushort(l1b)<<16) | __bfloat16_as_ushort(l0b);
}

// ------------------------------------------------- K1: qpb = h0@Wa.T+ba+bua
__global__ void qproj_kernel(const float* __restrict__ h0, const float* __restrict__ Wa,
                             const float* __restrict__ ba, const float* __restrict__ bua){
    int b = blockIdx.x;
    __shared__ float qS[HH];
    for (int k = threadIdx.x; k < HH; k += blockDim.x) qS[k] = h0[b*HH + k];
    __syncthreads();
    int h = threadIdx.x;
    if (h < HH){
        const float* w = Wa + h*HH;
        float s = ba[h] + bua[h];
        #pragma unroll 4
        for (int k = 0; k < HH; k++) s += qS[k]*w[k];
        d_qpb[b*HH + h] = s;
    }
}

// ---- K2 (mma.sync bf16 hi/lo): scores[b,t] = bva + sum_h Va[h]*tanh(qpb[b,h]+(Enc@Ua^T)[t,h])
__global__ void __launch_bounds__(NTHR)
scores_mma_kernel(const float* __restrict__ enc, const float* __restrict__ Ua,
                  const float* __restrict__ Va, const float* __restrict__ bva){
    extern __shared__ char sm[];
    uint32_t smb = smem_u32(sm);
    int tid  = threadIdx.x;
    int lane = tid & 31;
    int wid  = tid >> 5;
    int half = wid >> 3;            // 0: n-tiles 0..12, 1: n-tiles 13..25
    int m0   = (wid & 7) * 16;      // warp's m strip
    int tile0 = half ? 13 : 0;
    int b  = blockIdx.y;
    int t0 = blockIdx.x * BM;

    float* qbS = (float*)(sm + OFF_QB);
    float* vaS = (float*)(sm + OFF_VA);
    float* red = (float*)(sm + OFF_RED);
    for (int h = tid; h < HH; h += NTHR){ qbS[h] = d_qpb[b*HH + h]; vaS[h] = Va[h]; }

    float c[13][4];
    #pragma unroll
    for (int i=0;i<13;i++){ c[i][0]=0.f; c[i][1]=0.f; c[i][2]=0.f; c[i][3]=0.f; }

    const float* encB = enc + ((size_t)(b*TT + t0))*HH;

    // per-lane ldmatrix smem addresses (row part precomputed per chunk inside loop)
    int aRow = m0 + (lane & 15);
    int aKof = ((lane >> 4) & 1) * 16;
    int bRowL = lane & 7;
    int bKof = ((lane >> 3) & 1) * 16;

    for (int ch = 0; ch < NCHUNK; ch++){
        __syncthreads();   // all warps done reading previous chunk's smem
        // A chunk: Enc[t0..t0+128)[ch*64..+64) -> hi/lo bf16, padded rows
        for (int i = tid; i < BM*32; i += NTHR){
            int t = i >> 5, kp = i & 31;
            int gk = ch*KC + kp*2;
            float2 v = make_float2(0.f, 0.f);
            if (gk < HH) v = *reinterpret_cast<const float2*>(encB + (size_t)t*HH + gk);
            uint32_t hi, lo; split2(v, hi, lo);
            *(uint32_t*)(sm + OFF_AH + t*SROW + kp*4) = hi;
            *(uint32_t*)(sm + OFF_AL + t*SROW + kp*4) = lo;
        }
        // B chunk: Ua[n][ch*64..+64) (n rows 200..207 zero) -> hi/lo bf16
        for (int i = tid; i < NB*32; i += NTHR){
            int n = i >> 5, kp = i & 31;
            int gk = ch*KC + kp*2;
            float2 v = make_float2(0.f, 0.f);
            if (n < HH && gk < HH) v = *reinterpret_cast<const float2*>(Ua + (size_t)n*HH + gk);
            uint32_t hi, lo; split2(v, hi, lo);
            *(uint32_t*)(sm + OFF_BH + n*SROW + kp*4) = hi;
            *(uint32_t*)(sm + OFF_BL + n*SROW + kp*4) = lo;
        }
        __syncthreads();

        int nkt = (ch < 3) ? 4 : 1;   // chunk 3: only k 192..207
        for (int ks = 0; ks < nkt; ks++){
            uint32_t aHi[4], aLo[4];
            uint32_t aoff = (uint32_t)(aRow*SROW + ks*32 + aKof);
            ldsm_x4(aHi, smb + OFF_AH + aoff);
            ldsm_x4(aLo, smb + OFF_AL + aoff);
            #pragma unroll
            for (int nt = 0; nt < 13; nt++){
                uint32_t bHi[2], bLo[2];
                uint32_t boff = (uint32_t)(((tile0+nt)*8 + bRowL)*SROW + ks*32 + bKof);
                ldsm_x2(bHi, smb + OFF_BH + boff);
                ldsm_x2(bLo, smb + OFF_BL + boff);
                mma_bf16(c[nt], aHi, bHi);
                mma_bf16(c[nt], aHi, bLo);
                mma_bf16(c[nt], aLo, bHi);
            }
        }
    }

    // Epilogue: C frag thread l holds rows m0+(l>>2), +8; cols 2(l&3)+{0,1} per n-tile.
    float s0 = 0.f, s1 = 0.f;
    #pragma unroll
    for (int nt = 0; nt < 13; nt++){
        int h0 = (tile0+nt)*8 + (lane & 3)*2;
        if (h0 < HH){
            s0 += vaS[h0]  * fast_tanh(qbS[h0]  + c[nt][0]);
            s0 += vaS[h0+1]* fast_tanh(qbS[h0+1]+ c[nt][1]);
            s1 += vaS[h0]  * fast_tanh(qbS[h0]  + c[nt][2]);
            s1 += vaS[h0+1]* fast_tanh(qbS[h0+1]+ c[nt][3]);
        }
    }
    s0 += __shfl_xor_sync(0xFFFFFFFFu, s0, 1);
    s0 += __shfl_xor_sync(0xFFFFFFFFu, s0, 2);
    s1 += __shfl_xor_sync(0xFFFFFFFFu, s1, 1);
    s1 += __shfl_xor_sync(0xFFFFFFFFu, s1, 2);
    if ((lane & 3) == 0){
        int r0 = m0 + (lane >> 2);
        red[r0*2 + half]     = s0;
        red[(r0+8)*2 + half] = s1;
    }
    __syncthreads();
    if (tid < BM){
        d_scores[(size_t)b*TT + t0 + tid] = red[tid*2] + red[tid*2+1] + bva[0];
    }
}

// ---------------------------------------------------------- K3: softmax over T
__global__ void softmax_kernel(){
    int b = blockIdx.x;
    int tid = threadIdx.x;
    __shared__ float red[256];
    float v[8];
    float m = -1e30f;
    #pragma unroll
    for (int i=0;i<8;i++){ v[i] = d_scores[(size_t)b*TT + tid + i*256]; m = fmaxf(m, v[i]); }
    red[tid] = m; __syncthreads();
    for (int s=128; s>0; s>>=1){ if (tid<s) red[tid]=fmaxf(red[tid],red[tid+s]); __syncthreads(); }
    m = red[0]; __syncthreads();
    float sum=0.f;
    #pragma unroll
    for (int i=0;i<8;i++){ v[i]=__expf(v[i]-m); sum+=v[i]; }
    red[tid]=sum; __syncthreads();
    for (int s=128;s>0;s>>=1){ if(tid<s) red[tid]+=red[tid+s]; __syncthreads(); }
    float inv = 1.0f/red[0];
    #pragma unroll
    for (int i=0;i<8;i++) d_attn[(size_t)b*TT + tid + i*256] = v[i]*inv;
}

// ------------------------------------------- K4: context[b,h] = sum_t attn*enc
__global__ void context_kernel(const float* __restrict__ enc){
    int b = blockIdx.x;
    __shared__ float attnS[TT];
    for (int t = threadIdx.x; t < TT; t += blockDim.x) attnS[t] = d_attn[(size_t)b*TT + t];
    __syncthreads();
    int h = threadIdx.x;
    if (h < HH){
        const float* e = enc + (size_t)b*TT*HH + h;
        float a0=0,a1=0,a2=0,a3=0;
        #pragma unroll 4
        for (int t=0;t<TT;t+=4){
            a0 += attnS[t]   * e[(size_t)t*HH];
            a1 += attnS[t+1] * e[(size_t)(t+1)*HH];
            a2 += attnS[t+2] * e[(size_t)(t+2)*HH];
            a3 += attnS[t+3] * e[(size_t)(t+3)*HH];
        }
        d_ctx[b*HH+h] = (a0+a1)+(a2+a3);
    }
}

// --------- K5: 5 decoder steps (gates = gate_base + x*w0), LSTM cell, 200->100->50->1
__global__ void decoder_kernel(const float* __restrict__ x, const float* __restrict__ h0,
                               const float* __restrict__ c0,
                               const float* __restrict__ W_ih, const float* __restrict__ W_hh,
                               const float* __restrict__ b_ih, const float* __restrict__ b_hh,
                               const float* __restrict__ W1, const float* __restrict__ b1,
                               const float* __restrict__ W2, const float* __restrict__ b2,
                               const float* __restrict__ W3, const float* __restrict__ b3,
                               float* __restrict__ out){
    int b = blockIdx.x;
    int tid = threadIdx.x;
    __shared__ float ctxS[HH], h0S[HH], c0S[HH];
    __shared__ float gb[4*HH], w0[4*HH];
    __shared__ float hbuf[HH], o1[100], o2[50];
    __shared__ float xs;
    for (int k=tid;k<HH;k+=blockDim.x){
        ctxS[k]=d_ctx[b*HH+k]; h0S[k]=h0[b*HH+k]; c0S[k]=c0[b*HH+k];
    }
    if (tid==0) xs = x[b];
    __syncthreads();
    for (int j=tid; j<4*HH; j+=blockDim.x){
        const float* wih = W_ih + (size_t)j*(HH+1);
        const float* whh = W_hh + (size_t)j*HH;
        w0[j] = wih[0];
        float s = b_ih[j] + b_hh[j];
        #pragma unroll 4
        for (int k=0;k<HH;k++) s += ctxS[k]*wih[1+k] + h0S[k]*whh[k];
        gb[j] = s;
    }
    __syncthreads();
    for (int st=0; st<STEPS; st++){
        float xv = xs;
        if (tid < HH){
            float ig = gb[tid]      + xv*w0[tid];
            float fg = gb[HH+tid]   + xv*w0[HH+tid];
            float gg = gb[2*HH+tid] + xv*w0[2*HH+tid];
            float og = gb[3*HH+tid] + xv*w0[3*HH+tid];
            float c  = sigm(fg)*c0S[tid] + sigm(ig)*fast_tanh(gg);
            float hn = sigm(og)*fast_tanh(c);
            hbuf[tid] = fmaxf(hn, 0.0f);
        }
        __syncthreads();
        if (tid < 100){
            const float* w = W1 + tid*HH;
            float s1 = b1[tid];
            #pragma unroll 4
            for (int k=0;k<HH;k++) s1 += w[k]*hbuf[k];
            o1[tid] = fmaxf(s1, 0.0f);
        }
        __syncthreads();
        if (tid < 50){
            const float* w = W2 + tid*100;
            float s2 = b2[tid];
            #pragma unroll 4
            for (int k=0;k<100;k++) s2 += w[k]*o1[k];
            o2[tid] = fmaxf(s2, 0.0f);
        }
        __syncthreads();
        if (tid == 0){
            float y = b3[0];
            #pragma unroll
            for (int k=0;k<50;k++) y += W3[k]*o2[k];
            out[b*STEPS + st] = y;
            xs = y;
        }
        __syncthreads();
    }
}

extern "C" void kernel_launch(void* const* d_in, const int* in_sizes, int n_in,
                              void* d_out, int out_size){
    const float* x    = (const float*)d_in[0];
    const float* h0   = (const float*)d_in[1];
    const float* c0   = (const float*)d_in[2];
    const float* enc  = (const float*)d_in[3];
    const float* Wa   = (const float*)d_in[4];
    const float* ba   = (const float*)d_in[5];
    const float* Ua   = (const float*)d_in[6];
    const float* bua  = (const float*)d_in[7];
    const float* Va   = (const float*)d_in[8];
    const float* bva  = (const float*)d_in[9];
    const float* W_ih = (const float*)d_in[10];
    const float* W_hh = (const float*)d_in[11];
    const float* b_ih = (const float*)d_in[12];
    const float* b_hh = (const float*)d_in[13];
    const float* W1   = (const float*)d_in[14];
    const float* b1   = (const float*)d_in[15];
    const float* W2   = (const float*)d_in[16];
    const float* b2   = (const float*)d_in[17];
    const float* W3   = (const float*)d_in[18];
    const float* b3   = (const float*)d_in[19];
    float* out = (float*)d_out;

    static int smem_set = 0;
    if (!smem_set){
        cudaFuncSetAttribute(scores_mma_kernel,
                             cudaFuncAttributeMaxDynamicSharedMemorySize, SMEM_TOTAL);
        smem_set = 1;
    }

    qproj_kernel<<<BB, 256>>>(h0, Wa, ba, bua);
    dim3 g2(TT/BM, BB);
    scores_mma_kernel<<<g2, NTHR, SMEM_TOTAL>>>(enc, Ua, Va, bva);
    softmax_kernel<<<BB, 256>>>();
    context_kernel<<<BB, 256>>>(enc);
    decoder_kernel<<<BB, 256>>>(x, h0, c0, W_ih, W_hh, b_ih, b_hh, W1, b1, W2, b2, W3, b3, out);
}

// round 9
// speedup vs baseline: 2.1802x; 1.3105x over previous
#include <cuda_runtime.h>
#include <cuda_bf16.h>
#include <cstdint>
#include <math.h>

#define BB 128
#define TT 2048
#define HH 200
#define STEPS 5

// ---------------- mma.sync scores-GEMM geometry ----------------
#define BM      128              // t rows per CTA
#define KC      64               // bf16 k per smem chunk
#define NCHUNK  4                // k 0..255 (208 real+pad used)
#define NTHR    512              // 16 warps
#define NB      208              // padded n (h) rows in B smem (26 tiles of 8)
#define KP      208              // padded K in precomputed bf16 arrays
#define KP4     26               // uint4 per row (208 bf16)
#define SROW    144              // smem row stride bytes: conflict-free ldmatrix
// smem offsets
#define OFF_AH  0
#define OFF_AL  18432
#define OFF_BH  36864
#define OFF_BL  66816
#define OFF_QB  96768
#define OFF_VA  97568
#define OFF_RED 98368
#define SMEM_TOTAL 99392

#define NSEG 16                  // context t-segments

__device__ float d_qpb[BB*HH];
__device__ float d_scores[BB*TT];
__device__ float d_attn[BB*TT];
__device__ float d_ctx[BB*HH];
__device__ float d_ctxp[BB*NSEG*HH];
// precomputed bf16 hi/lo (2 bf16 packed per uint32)
__device__ uint32_t d_EncHi[(size_t)BB*TT*(KP/2)];
__device__ uint32_t d_EncLo[(size_t)BB*TT*(KP/2)];
__device__ uint32_t d_UaHi[NB*(KP/2)];
__device__ uint32_t d_UaLo[NB*(KP/2)];

__device__ __forceinline__ float fast_tanh(float x){
    float e = __expf(2.0f*x);
    return 1.0f - 2.0f/(e+1.0f);
}
__device__ __forceinline__ float sigm(float x){
    return 1.0f/(1.0f+__expf(-x));
}
__device__ __forceinline__ uint32_t smem_u32(const void* p){
    uint32_t a;
    asm("{ .reg .u64 t; cvta.to.shared.u64 t, %1; cvt.u32.u64 %0, t; }" : "=r"(a) : "l"(p));
    return a;
}
__device__ __forceinline__ void ldsm_x4(uint32_t* r, uint32_t addr){
    asm volatile("ldmatrix.sync.aligned.m8n8.x4.shared.b16 {%0,%1,%2,%3}, [%4];"
        : "=r"(r[0]),"=r"(r[1]),"=r"(r[2]),"=r"(r[3]) : "r"(addr));
}
__device__ __forceinline__ void ldsm_x2(uint32_t* r, uint32_t addr){
    asm volatile("ldmatrix.sync.aligned.m8n8.x2.shared.b16 {%0,%1}, [%2];"
        : "=r"(r[0]),"=r"(r[1]) : "r"(addr));
}
__device__ __forceinline__ void mma_bf16(float* c, const uint32_t* a, const uint32_t* b){
    asm volatile("mma.sync.aligned.m16n8k16.row.col.f32.bf16.bf16.f32 "
        "{%0,%1,%2,%3}, {%4,%5,%6,%7}, {%8,%9}, {%0,%1,%2,%3};"
        : "+f"(c[0]),"+f"(c[1]),"+f"(c[2]),"+f"(c[3])
        : "r"(a[0]),"r"(a[1]),"r"(a[2]),"r"(a[3]), "r"(b[0]),"r"(b[1]));
}
__device__ __forceinline__ void split2(float2 v, uint32_t& hi, uint32_t& lo){
    __nv_bfloat16 h0b = __float2bfloat16_rn(v.x), h1b = __float2bfloat16_rn(v.y);
    __nv_bfloat16 l0b = __float2bfloat16_rn(v.x - __bfloat162float(h0b));
    __nv_bfloat16 l1b = __float2bfloat16_rn(v.y - __bfloat162float(h1b));
    hi = ((uint32_t)__bfloat16_as_ushort(h1b)<<16) | __bfloat16_as_ushort(h0b);
    lo = ((uint32_t)__bfloat16_as_ushort(l1b)<<16) | __bfloat16_as_ushort(l0b);
}
__device__ __forceinline__ void cpa16(uint32_t dst, const void* src){
    asm volatile("cp.async.ca.shared.global [%0], [%1], 16;" :: "r"(dst), "l"(src));
}
#define CP_COMMIT() asm volatile("cp.async.commit_group;" ::: "memory")
#define CP_WAIT0()  asm volatile("cp.async.wait_group 0;" ::: "memory")

// -------------------------------------------- K0a: Ua -> bf16 hi/lo padded [208][208]
__global__ void conv_ua(const float* __restrict__ Ua){
    int idx = blockIdx.x*blockDim.x + threadIdx.x;   // over NB * 104
    if (idx < NB*(KP/2)){
        int n = idx / (KP/2), kq = idx % (KP/2);
        int gk = kq*2;
        float2 v = make_float2(0.f, 0.f);
        if (n < HH && gk < HH) v = *reinterpret_cast<const float2*>(Ua + (size_t)n*HH + gk);
        uint32_t hi, lo; split2(v, hi, lo);
        d_UaHi[idx] = hi; d_UaLo[idx] = lo;
    }
}
// -------------------------------------------- K0b: enc -> bf16 hi/lo padded [B*T][208]
__global__ void conv_enc(const float* __restrict__ enc){
    size_t idx = (size_t)blockIdx.x*blockDim.x + threadIdx.x;  // over B*T*104
    if (idx < (size_t)BB*TT*(KP/2)){
        size_t row = idx / (KP/2);
        int kq = (int)(idx % (KP/2));
        int gk = kq*2;
        float2 v = make_float2(0.f, 0.f);
        if (gk < HH) v = *reinterpret_cast<const float2*>(enc + row*HH + gk);
        uint32_t hi, lo; split2(v, hi, lo);
        d_EncHi[idx] = hi; d_EncLo[idx] = lo;
    }
}

// ------------------------------------------------- K1: qpb = h0@Wa.T+ba+bua
__global__ void qproj_kernel(const float* __restrict__ h0, const float* __restrict__ Wa,
                             const float* __restrict__ ba, const float* __restrict__ bua){
    int b = blockIdx.x;
    __shared__ float qS[HH];
    for (int k = threadIdx.x; k < HH; k += blockDim.x) qS[k] = h0[b*HH + k];
    __syncthreads();
    int h = threadIdx.x;
    if (h < HH){
        const float* w = Wa + h*HH;
        float s = ba[h] + bua[h];
        #pragma unroll 4
        for (int k = 0; k < HH; k++) s += qS[k]*w[k];
        d_qpb[b*HH + h] = s;
    }
}

// ---- K2 (mma.sync bf16 hi/lo): scores[b,t] = bva + sum_h Va[h]*tanh(qpb[b,h]+(Enc@Ua^T)[t,h])
__global__ void __launch_bounds__(NTHR)
scores_mma_kernel(const float* __restrict__ Va, const float* __restrict__ bva){
    extern __shared__ char sm[];
    uint32_t smb = smem_u32(sm);
    int tid  = threadIdx.x;
    int lane = tid & 31;
    int wid  = tid >> 5;
    int half = wid >> 3;
    int m0   = (wid & 7) * 16;
    int tile0 = half ? 13 : 0;
    int b  = blockIdx.y;
    int t0 = blockIdx.x * BM;
    size_t rowA0 = (size_t)(b*TT + t0);

    float* qbS = (float*)(sm + OFF_QB);
    float* vaS = (float*)(sm + OFF_VA);
    float* red = (float*)(sm + OFF_RED);
    for (int h = tid; h < HH; h += NTHR){ qbS[h] = d_qpb[b*HH + h]; vaS[h] = Va[h]; }

    float c[13][4];
    #pragma unroll
    for (int i=0;i<13;i++){ c[i][0]=0.f; c[i][1]=0.f; c[i][2]=0.f; c[i][3]=0.f; }

    const uint4* encHi4 = reinterpret_cast<const uint4*>(d_EncHi);
    const uint4* encLo4 = reinterpret_cast<const uint4*>(d_EncLo);
    const uint4* uaHi4  = reinterpret_cast<const uint4*>(d_UaHi);
    const uint4* uaLo4  = reinterpret_cast<const uint4*>(d_UaLo);

    int aRow = m0 + (lane & 15);
    int aKof = ((lane >> 4) & 1) * 16;
    int bRowL = lane & 7;
    int bKof = ((lane >> 3) & 1) * 16;

    for (int ch = 0; ch < NCHUNK; ch++){
        __syncthreads();   // prev chunk's MMAs finished reading smem
        int jmax = (ch < 3) ? 8 : 2;   // chunk 3 only holds uint4 24..25 (k192..207)
        for (int i = tid; i < BM*jmax; i += NTHR){
            int t = i / jmax, j = i % jmax;
            const uint4* sH = encHi4 + (rowA0 + t)*KP4 + ch*8 + j;
            const uint4* sL = encLo4 + (rowA0 + t)*KP4 + ch*8 + j;
            cpa16(smb + OFF_AH + t*SROW + j*16, sH);
            cpa16(smb + OFF_AL + t*SROW + j*16, sL);
        }
        for (int i = tid; i < NB*jmax; i += NTHR){
            int n = i / jmax, j = i % jmax;
            cpa16(smb + OFF_BH + n*SROW + j*16, uaHi4 + n*KP4 + ch*8 + j);
            cpa16(smb + OFF_BL + n*SROW + j*16, uaLo4 + n*KP4 + ch*8 + j);
        }
        CP_COMMIT();
        CP_WAIT0();
        __syncthreads();

        int nkt = (ch < 3) ? 4 : 1;
        for (int ks = 0; ks < nkt; ks++){
            uint32_t aHi[4], aLo[4];
            uint32_t aoff = (uint32_t)(aRow*SROW + ks*32 + aKof);
            ldsm_x4(aHi, smb + OFF_AH + aoff);
            ldsm_x4(aLo, smb + OFF_AL + aoff);
            #pragma unroll
            for (int nt = 0; nt < 13; nt++){
                uint32_t bHi[2], bLo[2];
                uint32_t boff = (uint32_t)(((tile0+nt)*8 + bRowL)*SROW + ks*32 + bKof);
                ldsm_x2(bHi, smb + OFF_BH + boff);
                ldsm_x2(bLo, smb + OFF_BL + boff);
                mma_bf16(c[nt], aHi, bHi);
                mma_bf16(c[nt], aHi, bLo);
                mma_bf16(c[nt], aLo, bHi);
            }
        }
    }

    // Epilogue: C frag thread l holds rows m0+(l>>2), +8; cols 2(l&3)+{0,1} per n-tile.
    float s0 = 0.f, s1 = 0.f;
    #pragma unroll
    for (int nt = 0; nt < 13; nt++){
        int h0 = (tile0+nt)*8 + (lane & 3)*2;
        if (h0 < HH){
            s0 += vaS[h0]  * fast_tanh(qbS[h0]  + c[nt][0]);
            s0 += vaS[h0+1]* fast_tanh(qbS[h0+1]+ c[nt][1]);
            s1 += vaS[h0]  * fast_tanh(qbS[h0]  + c[nt][2]);
            s1 += vaS[h0+1]* fast_tanh(qbS[h0+1]+ c[nt][3]);
        }
    }
    s0 += __shfl_xor_sync(0xFFFFFFFFu, s0, 1);
    s0 += __shfl_xor_sync(0xFFFFFFFFu, s0, 2);
    s1 += __shfl_xor_sync(0xFFFFFFFFu, s1, 1);
    s1 += __shfl_xor_sync(0xFFFFFFFFu, s1, 2);
    if ((lane & 3) == 0){
        int r0 = m0 + (lane >> 2);
        red[r0*2 + half]     = s0;
        red[(r0+8)*2 + half] = s1;
    }
    __syncthreads();
    if (tid < BM){
        d_scores[(size_t)b*TT + t0 + tid] = red[tid*2] + red[tid*2+1] + bva[0];
    }
}

// ---------------------------------------------------------- K3: softmax over T
__global__ void softmax_kernel(){
    int b = blockIdx.x;
    int tid = threadIdx.x;
    __shared__ float red[256];
    float v[8];
    float m = -1e30f;
    #pragma unroll
    for (int i=0;i<8;i++){ v[i] = d_scores[(size_t)b*TT + tid + i*256]; m = fmaxf(m, v[i]); }
    red[tid] = m; __syncthreads();
    for (int s=128; s>0; s>>=1){ if (tid<s) red[tid]=fmaxf(red[tid],red[tid+s]); __syncthreads(); }
    m = red[0]; __syncthreads();
    float sum=0.f;
    #pragma unroll
    for (int i=0;i<8;i++){ v[i]=__expf(v[i]-m); sum+=v[i]; }
    red[tid]=sum; __syncthreads();
    for (int s=128;s>0;s>>=1){ if(tid<s) red[tid]+=red[tid+s]; __syncthreads(); }
    float inv = 1.0f/red[0];
    #pragma unroll
    for (int i=0;i<8;i++) d_attn[(size_t)b*TT + tid + i*256] = v[i]*inv;
}

// -------------------- K4a: partial context over t-segments (grid BB x NSEG)
__global__ void context_part(const float* __restrict__ enc){
    int b = blockIdx.x, seg = blockIdx.y;
    const int TS = TT/NSEG;   // 128
    __shared__ float attnS[TS];
    int t00 = seg*TS;
    if (threadIdx.x < TS) attnS[threadIdx.x] = d_attn[(size_t)b*TT + t00 + threadIdx.x];
    __syncthreads();
    int h = threadIdx.x;
    if (h < HH){
        const float* e = enc + (size_t)b*TT*HH + (size_t)t00*HH + h;
        float a0=0,a1=0,a2=0,a3=0;
        #pragma unroll 4
        for (int t=0;t<TS;t+=4){
            a0 += attnS[t]   * e[(size_t)t*HH];
            a1 += attnS[t+1] * e[(size_t)(t+1)*HH];
            a2 += attnS[t+2] * e[(size_t)(t+2)*HH];
            a3 += attnS[t+3] * e[(size_t)(t+3)*HH];
        }
        d_ctxp[(b*NSEG + seg)*HH + h] = (a0+a1)+(a2+a3);
    }
}
// -------------------- K4b: reduce partials
__global__ void context_reduce(){
    int b = blockIdx.x, h = threadIdx.x;
    if (h < HH){
        float s = 0.f;
        #pragma unroll
        for (int i=0;i<NSEG;i++) s += d_ctxp[(b*NSEG + i)*HH + h];
        d_ctx[b*HH + h] = s;
    }
}

// --------- K5: 5 decoder steps (gates = gate_base + x*w0), LSTM cell, 200->100->50->1
__global__ void decoder_kernel(const float* __restrict__ x, const float* __restrict__ h0,
                               const float* __restrict__ c0,
                               const float* __restrict__ W_ih, const float* __restrict__ W_hh,
                               const float* __restrict__ b_ih, const float* __restrict__ b_hh,
                               const float* __restrict__ W1, const float* __restrict__ b1,
                               const float* __restrict__ W2, const float* __restrict__ b2,
                               const float* __restrict__ W3, const float* __restrict__ b3,
                               float* __restrict__ out){
    int b = blockIdx.x;
    int tid = threadIdx.x;
    __shared__ float ctxS[HH], h0S[HH], c0S[HH];
    __shared__ float gb[4*HH], w0[4*HH];
    __shared__ float hbuf[HH], o1[100], o2[50];
    __shared__ float xs;
    for (int k=tid;k<HH;k+=blockDim.x){
        ctxS[k]=d_ctx[b*HH+k]; h0S[k]=h0[b*HH+k]; c0S[k]=c0[b*HH+k];
    }
    if (tid==0) xs = x[b];
    __syncthreads();
    for (int j=tid; j<4*HH; j+=blockDim.x){
        const float* wih = W_ih + (size_t)j*(HH+1);
        const float* whh = W_hh + (size_t)j*HH;
        w0[j] = wih[0];
        float s = b_ih[j] + b_hh[j];
        #pragma unroll 4
        for (int k=0;k<HH;k++) s += ctxS[k]*wih[1+k] + h0S[k]*whh[k];
        gb[j] = s;
    }
    __syncthreads();
    for (int st=0; st<STEPS; st++){
        float xv = xs;
        if (tid < HH){
            float ig = gb[tid]      + xv*w0[tid];
            float fg = gb[HH+tid]   + xv*w0[HH+tid];
            float gg = gb[2*HH+tid] + xv*w0[2*HH+tid];
            float og = gb[3*HH+tid] + xv*w0[3*HH+tid];
            float c  = sigm(fg)*c0S[tid] + sigm(ig)*fast_tanh(gg);
            float hn = sigm(og)*fast_tanh(c);
            hbuf[tid] = fmaxf(hn, 0.0f);
        }
        __syncthreads();
        if (tid < 100){
            const float* w = W1 + tid*HH;
            float s1 = b1[tid];
            #pragma unroll 4
            for (int k=0;k<HH;k++) s1 += w[k]*hbuf[k];
            o1[tid] = fmaxf(s1, 0.0f);
        }
        __syncthreads();
        if (tid < 50){
            const float* w = W2 + tid*100;
            float s2 = b2[tid];
            #pragma unroll 4
            for (int k=0;k<100;k++) s2 += w[k]*o1[k];
            o2[tid] = fmaxf(s2, 0.0f);
        }
        __syncthreads();
        if (tid == 0){
            float y = b3[0];
            #pragma unroll
            for (int k=0;k<50;k++) y += W3[k]*o2[k];
            out[b*STEPS + st] = y;
            xs = y;
        }
        __syncthreads();
    }
}

extern "C" void kernel_launch(void* const* d_in, const int* in_sizes, int n_in,
                              void* d_out, int out_size){
    const float* x    = (const float*)d_in[0];
    const float* h0   = (const float*)d_in[1];
    const float* c0   = (const float*)d_in[2];
    const float* enc  = (const float*)d_in[3];
    const float* Wa   = (const float*)d_in[4];
    const float* ba   = (const float*)d_in[5];
    const float* Ua   = (const float*)d_in[6];
    const float* bua  = (const float*)d_in[7];
    const float* Va   = (const float*)d_in[8];
    const float* bva  = (const float*)d_in[9];
    const float* W_ih = (const float*)d_in[10];
    const float* W_hh = (const float*)d_in[11];
    const float* b_ih = (const float*)d_in[12];
    const float* b_hh = (const float*)d_in[13];
    const float* W1   = (const float*)d_in[14];
    const float* b1   = (const float*)d_in[15];
    const float* W2   = (const float*)d_in[16];
    const float* b2   = (const float*)d_in[17];
    const float* W3   = (const float*)d_in[18];
    const float* b3   = (const float*)d_in[19];
    float* out = (float*)d_out;

    static int smem_set = 0;
    if (!smem_set){
        cudaFuncSetAttribute(scores_mma_kernel,
                             cudaFuncAttributeMaxDynamicSharedMemorySize, SMEM_TOTAL);
        smem_set = 1;
    }

    conv_ua<<<(NB*(KP/2)+255)/256, 256>>>(Ua);
    {
        size_t tot = (size_t)BB*TT*(KP/2);
        conv_enc<<<(unsigned)((tot+255)/256), 256>>>(enc);
    }
    qproj_kernel<<<BB, 256>>>(h0, Wa, ba, bua);
    dim3 g2(TT/BM, BB);
    scores_mma_kernel<<<g2, NTHR, SMEM_TOTAL>>>(Va, bva);
    softmax_kernel<<<BB, 256>>>();
    dim3 g4(BB, NSEG);
    context_part<<<g4, 256>>>(enc);
    context_reduce<<<BB, 256>>>();
    decoder_kernel<<<BB, 256>>>(x, h0, c0, W_ih, W_hh, b_ih, b_hh, W1, b1, W2, b2, W3, b3, out);
}

// round 11
// speedup vs baseline: 2.2621x; 1.0376x over previous
#include <cuda_runtime.h>
#include <cuda_bf16.h>
#include <cstdint>
#include <math.h>

#define BB 128
#define TT 2048
#define HH 200
#define STEPS 5

// ---------------- mma.sync scores-GEMM geometry ----------------
#define BM      128
#define KC      64
#define NCHUNK  4
#define NTHR    512
#define NB      208
#define KP      208
#define KP4     26
#define SROW    144
// double-buffered smem: per-stage offsets
#define SSTG    96768
#define OFF_AH  0
#define OFF_AL  18432
#define OFF_BH  36864
#define OFF_BL  66816
#define OFF_QB  193536
#define OFF_VA  194336
#define OFF_RED 195136
#define SMEM_TOTAL 196160

#define NSEG 16

__device__ float d_qpb[BB*HH];
__device__ float d_scores[BB*TT];
__device__ float d_attn[BB*TT];
__device__ float d_ctx[BB*HH];
__device__ float d_ctxp[BB*NSEG*HH];
__device__ uint32_t d_EncHi[(size_t)BB*TT*(KP/2)];
__device__ uint32_t d_EncLo[(size_t)BB*TT*(KP/2)];
__device__ uint32_t d_UaHi[NB*(KP/2)];
__device__ uint32_t d_UaLo[NB*(KP/2)];

__device__ __forceinline__ float fast_tanh(float x){
    float e = __expf(2.0f*x);
    return 1.0f - 2.0f/(e+1.0f);
}
__device__ __forceinline__ float sigm(float x){
    return 1.0f/(1.0f+__expf(-x));
}
__device__ __forceinline__ uint32_t smem_u32(const void* p){
    uint32_t a;
    asm("{ .reg .u64 t; cvta.to.shared.u64 t, %1; cvt.u32.u64 %0, t; }" : "=r"(a) : "l"(p));
    return a;
}
__device__ __forceinline__ void ldsm_x4(uint32_t* r, uint32_t addr){
    asm volatile("ldmatrix.sync.aligned.m8n8.x4.shared.b16 {%0,%1,%2,%3}, [%4];"
        : "=r"(r[0]),"=r"(r[1]),"=r"(r[2]),"=r"(r[3]) : "r"(addr));
}
__device__ __forceinline__ void ldsm_x2(uint32_t* r, uint32_t addr){
    asm volatile("ldmatrix.sync.aligned.m8n8.x2.shared.b16 {%0,%1}, [%2];"
        : "=r"(r[0]),"=r"(r[1]) : "r"(addr));
}
__device__ __forceinline__ void mma_bf16(float* c, const uint32_t* a, const uint32_t* b){
    asm volatile("mma.sync.aligned.m16n8k16.row.col.f32.bf16.bf16.f32 "
        "{%0,%1,%2,%3}, {%4,%5,%6,%7}, {%8,%9}, {%0,%1,%2,%3};"
        : "+f"(c[0]),"+f"(c[1]),"+f"(c[2]),"+f"(c[3])
        : "r"(a[0]),"r"(a[1]),"r"(a[2]),"r"(a[3]), "r"(b[0]),"r"(b[1]));
}
__device__ __forceinline__ void split1(float v, uint32_t& hi16, uint32_t& lo16){
    __nv_bfloat16 hb = __float2bfloat16_rn(v);
    __nv_bfloat16 lb = __float2bfloat16_rn(v - __bfloat162float(hb));
    hi16 = __bfloat16_as_ushort(hb);
    lo16 = __bfloat16_as_ushort(lb);
}
__device__ __forceinline__ void cpa16(uint32_t dst, const void* src){
    asm volatile("cp.async.ca.shared.global [%0], [%1], 16;" :: "r"(dst), "l"(src));
}
#define CP_COMMIT()  asm volatile("cp.async.commit_group;" ::: "memory")
#define CP_WAIT(n)   asm volatile("cp.async.wait_group %0;" :: "n"(n) : "memory")

// -------------------- K0a: Ua -> bf16 hi/lo padded [208][208]
__global__ void conv_ua(const float* __restrict__ Ua){
    int idx = blockIdx.x*blockDim.x + threadIdx.x;
    if (idx < NB*(KP/2)){
        int n = idx / (KP/2), kq = idx % (KP/2);
        int gk = kq*2;
        float2 v = make_float2(0.f, 0.f);
        if (n < HH && gk < HH) v = *reinterpret_cast<const float2*>(Ua + (size_t)n*HH + gk);
        uint32_t h0,l0,h1,l1;
        split1(v.x,h0,l0); split1(v.y,h1,l1);
        d_UaHi[idx] = (h1<<16)|h0; d_UaLo[idx] = (l1<<16)|l0;
    }
}
// -------------------- K0b: enc -> bf16 hi/lo padded, uint4-vectorized
__global__ void conv_enc(const float* __restrict__ enc){
    size_t idx = (size_t)blockIdx.x*blockDim.x + threadIdx.x;  // over B*T*KP4 uint4
    if (idx >= (size_t)BB*TT*KP4) return;
    size_t row = idx / KP4;
    int q4 = (int)(idx % KP4);          // uint4 index: 8 bf16 = 8 k
    int gk = q4*8;
    float v[8];
    const float* base = enc + row*HH + gk;
    #pragma unroll
    for (int i=0;i<8;i++) v[i] = (gk+i < HH) ? base[i] : 0.f;
    uint32_t hi[8], lo[8];
    #pragma unroll
    for (int i=0;i<8;i++) split1(v[i], hi[i], lo[i]);
    uint4 H, L;
    H.x=(hi[1]<<16)|hi[0]; H.y=(hi[3]<<16)|hi[2]; H.z=(hi[5]<<16)|hi[4]; H.w=(hi[7]<<16)|hi[6];
    L.x=(lo[1]<<16)|lo[0]; L.y=(lo[3]<<16)|lo[2]; L.z=(lo[5]<<16)|lo[4]; L.w=(lo[7]<<16)|lo[6];
    reinterpret_cast<uint4*>(d_EncHi)[idx] = H;
    reinterpret_cast<uint4*>(d_EncLo)[idx] = L;
}

// ------------------------------------------------- K1: qpb = h0@Wa.T+ba+bua
__global__ void qproj_kernel(const float* __restrict__ h0, const float* __restrict__ Wa,
                             const float* __restrict__ ba, const float* __restrict__ bua){
    int b = blockIdx.x;
    __shared__ float qS[HH];
    for (int k = threadIdx.x; k < HH; k += blockDim.x) qS[k] = h0[b*HH + k];
    __syncthreads();
    int h = threadIdx.x;
    if (h < HH){
        const float* w = Wa + h*HH;
        float s = ba[h] + bua[h];
        #pragma unroll 4
        for (int k = 0; k < HH; k++) s += qS[k]*w[k];
        d_qpb[b*HH + h] = s;
    }
}

// ---- K2: double-buffered cp.async pipeline + mma.sync bf16 hi/lo
__global__ void __launch_bounds__(NTHR)
scores_mma_kernel(const float* __restrict__ Va, const float* __restrict__ bva){
    extern __shared__ char sm[];
    uint32_t smb = smem_u32(sm);
    int tid  = threadIdx.x;
    int lane = tid & 31;
    int wid  = tid >> 5;
    int half = wid >> 3;
    int m0   = (wid & 7) * 16;
    int tile0 = half ? 13 : 0;
    int b  = blockIdx.y;
    int t0 = blockIdx.x * BM;
    size_t rowA0 = (size_t)(b*TT + t0);

    float* qbS = (float*)(sm + OFF_QB);
    float* vaS = (float*)(sm + OFF_VA);
    float* red = (float*)(sm + OFF_RED);
    for (int h = tid; h < HH; h += NTHR){ qbS[h] = d_qpb[b*HH + h]; vaS[h] = Va[h]; }

    float c[13][4];
    #pragma unroll
    for (int i=0;i<13;i++){ c[i][0]=0.f; c[i][1]=0.f; c[i][2]=0.f; c[i][3]=0.f; }

    const uint4* encHi4 = reinterpret_cast<const uint4*>(d_EncHi);
    const uint4* encLo4 = reinterpret_cast<const uint4*>(d_EncLo);
    const uint4* uaHi4  = reinterpret_cast<const uint4*>(d_UaHi);
    const uint4* uaLo4  = reinterpret_cast<const uint4*>(d_UaLo);

    int aRow = m0 + (lane & 15);
    int aKof = ((lane >> 4) & 1) * 16;

    // B pair-tile ldsm_x4 address pieces: lane -> matrix lane>>3, row lane&7
    int bPairTileOff = (lane >> 4);        // +0/+1 within pair
    int bPairKof  = ((lane >> 3) & 1) * 16;
    int bPairRow  = lane & 7;
    // last-tile ldsm_x2: lanes 0..15
    int bRowL = lane & 7;
    int bKofL = ((lane >> 3) & 1) * 16;

    // ---- chunk loader (cp.async) ----
    auto load_chunk = [&](int ch, int stg){
        uint32_t sb = smb + stg*SSTG;
        int jmax = (ch < 3) ? 8 : 2;
        for (int i = tid; i < BM*jmax; i += NTHR){
            int t = i / jmax, j = i % jmax;
            cpa16(sb + OFF_AH + t*SROW + j*16, encHi4 + (rowA0 + t)*KP4 + ch*8 + j);
            cpa16(sb + OFF_AL + t*SROW + j*16, encLo4 + (rowA0 + t)*KP4 + ch*8 + j);
        }
        for (int i = tid; i < NB*jmax; i += NTHR){
            int n = i / jmax, j = i % jmax;
            cpa16(sb + OFF_BH + n*SROW + j*16, uaHi4 + n*KP4 + ch*8 + j);
            cpa16(sb + OFF_BL + n*SROW + j*16, uaLo4 + n*KP4 + ch*8 + j);
        }
    };

    load_chunk(0, 0);
    CP_COMMIT();

    for (int ch = 0; ch < NCHUNK; ch++){
        if (ch < NCHUNK-1){ load_chunk(ch+1, (ch+1)&1); CP_COMMIT(); }
        if (ch < NCHUNK-1) CP_WAIT(1); else CP_WAIT(0);
        __syncthreads();

        uint32_t sb = smb + (ch&1)*SSTG;
        int nkt = (ch < 3) ? 4 : 1;
        for (int ks = 0; ks < nkt; ks++){
            uint32_t aHi[4], aLo[4];
            uint32_t aoff = (uint32_t)(aRow*SROW + ks*32 + aKof);
            ldsm_x4(aHi, sb + OFF_AH + aoff);
            ldsm_x4(aLo, sb + OFF_AL + aoff);
            #pragma unroll
            for (int p = 0; p < 6; p++){
                uint32_t bHi[4], bLo[4];
                uint32_t boff = (uint32_t)((((tile0 + 2*p + bPairTileOff)*8) + bPairRow)*SROW
                                           + ks*32 + bPairKof);
                ldsm_x4(bHi, sb + OFF_BH + boff);
                ldsm_x4(bLo, sb + OFF_BL + boff);
                mma_bf16(c[2*p],   aHi, bHi);
                mma_bf16(c[2*p],   aHi, bLo);
                mma_bf16(c[2*p],   aLo, bHi);
                mma_bf16(c[2*p+1], aHi, bHi+2);
                mma_bf16(c[2*p+1], aHi, bLo+2);
                mma_bf16(c[2*p+1], aLo, bHi+2);
            }
            {   // last tile (nt=12)
                uint32_t bHi[2], bLo[2];
                uint32_t boff = (uint32_t)(((tile0+12)*8 + bRowL)*SROW + ks*32 + bKofL);
                ldsm_x2(bHi, sb + OFF_BH + boff);
                ldsm_x2(bLo, sb + OFF_BL + boff);
                mma_bf16(c[12], aHi, bHi);
                mma_bf16(c[12], aHi, bLo);
                mma_bf16(c[12], aLo, bHi);
            }
        }
        __syncthreads();
    }

    // Epilogue
    float s0 = 0.f, s1 = 0.f;
    #pragma unroll
    for (int nt = 0; nt < 13; nt++){
        int h0 = (tile0+nt)*8 + (lane & 3)*2;
        if (h0 < HH){
            s0 += vaS[h0]  * fast_tanh(qbS[h0]  + c[nt][0]);
            s0 += vaS[h0+1]* fast_tanh(qbS[h0+1]+ c[nt][1]);
            s1 += vaS[h0]  * fast_tanh(qbS[h0]  + c[nt][2]);
            s1 += vaS[h0+1]* fast_tanh(qbS[h0+1]+ c[nt][3]);
        }
    }
    s0 += __shfl_xor_sync(0xFFFFFFFFu, s0, 1);
    s0 += __shfl_xor_sync(0xFFFFFFFFu, s0, 2);
    s1 += __shfl_xor_sync(0xFFFFFFFFu, s1, 1);
    s1 += __shfl_xor_sync(0xFFFFFFFFu, s1, 2);
    if ((lane & 3) == 0){
        int r0 = m0 + (lane >> 2);
        red[r0*2 + half]     = s0;
        red[(r0+8)*2 + half] = s1;
    }
    __syncthreads();
    if (tid < BM){
        d_scores[(size_t)b*TT + t0 + tid] = red[tid*2] + red[tid*2+1] + bva[0];
    }
}

// ---------------------------------------------------------- K3: softmax over T
__global__ void softmax_kernel(){
    int b = blockIdx.x;
    int tid = threadIdx.x;
    __shared__ float red[256];
    float v[8];
    float m = -1e30f;
    #pragma unroll
    for (int i=0;i<8;i++){ v[i] = d_scores[(size_t)b*TT + tid + i*256]; m = fmaxf(m, v[i]); }
    red[tid] = m; __syncthreads();
    for (int s=128; s>0; s>>=1){ if (tid<s) red[tid]=fmaxf(red[tid],red[tid+s]); __syncthreads(); }
    m = red[0]; __syncthreads();
    float sum=0.f;
    #pragma unroll
    for (int i=0;i<8;i++){ v[i]=__expf(v[i]-m); sum+=v[i]; }
    red[tid]=sum; __syncthreads();
    for (int s=128;s>0;s>>=1){ if(tid<s) red[tid]+=red[tid+s]; __syncthreads(); }
    float inv = 1.0f/red[0];
    #pragma unroll
    for (int i=0;i<8;i++) d_attn[(size_t)b*TT + tid + i*256] = v[i]*inv;
}

// -------------------- K4a: partial context over t-segments (grid BB x NSEG)
__global__ void context_part(const float* __restrict__ enc){
    int b = blockIdx.x, seg = blockIdx.y;
    const int TS = TT/NSEG;
    __shared__ float attnS[TS];
    int t00 = seg*TS;
    if (threadIdx.x < TS) attnS[threadIdx.x] = d_attn[(size_t)b*TT + t00 + threadIdx.x];
    __syncthreads();
    int h = threadIdx.x;
    if (h < HH){
        const float* e = enc + (size_t)b*TT*HH + (size_t)t00*HH + h;
        float a0=0,a1=0,a2=0,a3=0;
        #pragma unroll 4
        for (int t=0;t<TS;t+=4){
            a0 += attnS[t]   * e[(size_t)t*HH];
            a1 += attnS[t+1] * e[(size_t)(t+1)*HH];
            a2 += attnS[t+2] * e[(size_t)(t+2)*HH];
            a3 += attnS[t+3] * e[(size_t)(t+3)*HH];
        }
        d_ctxp[(b*NSEG + seg)*HH + h] = (a0+a1)+(a2+a3);
    }
}
// -------------------- K4b: reduce partials
__global__ void context_reduce(){
    int b = blockIdx.x, h = threadIdx.x;
    if (h < HH){
        float s = 0.f;
        #pragma unroll
        for (int i=0;i<NSEG;i++) s += d_ctxp[(b*NSEG + i)*HH + h];
        d_ctx[b*HH + h] = s;
    }
}

// --------- K5: decoder steps
__global__ void decoder_kernel(const float* __restrict__ x, const float* __restrict__ h0,
                               const float* __restrict__ c0,
                               const float* __restrict__ W_ih, const float* __restrict__ W_hh,
                               const float* __restrict__ b_ih, const float* __restrict__ b_hh,
                               const float* __restrict__ W1, const float* __restrict__ b1,
                               const float* __restrict__ W2, const float* __restrict__ b2,
                               const float* __restrict__ W3, const float* __restrict__ b3,
                               float* __restrict__ out){
    int b = blockIdx.x;
    int tid = threadIdx.x;
    __shared__ float ctxS[HH], h0S[HH], c0S[HH];
    __shared__ float gb[4*HH], w0[4*HH];
    __shared__ float hbuf[HH], o1[100], o2[50];
    __shared__ float xs;
    for (int k=tid;k<HH;k+=blockDim.x){
        ctxS[k]=d_ctx[b*HH+k]; h0S[k]=h0[b*HH+k]; c0S[k]=c0[b*HH+k];
    }
    if (tid==0) xs = x[b];
    __syncthreads();
    for (int j=tid; j<4*HH; j+=blockDim.x){
        const float* wih = W_ih + (size_t)j*(HH+1);
        const float* whh = W_hh + (size_t)j*HH;
        w0[j] = wih[0];
        float s = b_ih[j] + b_hh[j];
        #pragma unroll 4
        for (int k=0;k<HH;k++) s += ctxS[k]*wih[1+k] + h0S[k]*whh[k];
        gb[j] = s;
    }
    __syncthreads();
    for (int st=0; st<STEPS; st++){
        float xv = xs;
        if (tid < HH){
            float ig = gb[tid]      + xv*w0[tid];
            float fg = gb[HH+tid]   + xv*w0[HH+tid];
            float gg = gb[2*HH+tid] + xv*w0[2*HH+tid];
            float og = gb[3*HH+tid] + xv*w0[3*HH+tid];
            float c  = sigm(fg)*c0S[tid] + sigm(ig)*fast_tanh(gg);
            float hn = sigm(og)*fast_tanh(c);
            hbuf[tid] = fmaxf(hn, 0.0f);
        }
        __syncthreads();
        if (tid < 100){
            const float* w = W1 + tid*HH;
            float s1 = b1[tid];
            #pragma unroll 4
            for (int k=0;k<HH;k++) s1 += w[k]*hbuf[k];
            o1[tid] = fmaxf(s1, 0.0f);
        }
        __syncthreads();
        if (tid < 50){
            const float* w = W2 + tid*100;
            float s2 = b2[tid];
            #pragma unroll 4
            for (int k=0;k<100;k++) s2 += w[k]*o1[k];
            o2[tid] = fmaxf(s2, 0.0f);
        }
        __syncthreads();
        if (tid == 0){
            float y = b3[0];
            #pragma unroll
            for (int k=0;k<50;k++) y += W3[k]*o2[k];
            out[b*STEPS + st] = y;
            xs = y;
        }
        __syncthreads();
    }
}

extern "C" void kernel_launch(void* const* d_in, const int* in_sizes, int n_in,
                              void* d_out, int out_size){
    const float* x    = (const float*)d_in[0];
    const float* h0   = (const float*)d_in[1];
    const float* c0   = (const float*)d_in[2];
    const float* enc  = (const float*)d_in[3];
    const float* Wa   = (const float*)d_in[4];
    const float* ba   = (const float*)d_in[5];
    const float* Ua   = (const float*)d_in[6];
    const float* bua  = (const float*)d_in[7];
    const float* Va   = (const float*)d_in[8];
    const float* bva  = (const float*)d_in[9];
    const float* W_ih = (const float*)d_in[10];
    const float* W_hh = (const float*)d_in[11];
    const float* b_ih = (const float*)d_in[12];
    const float* b_hh = (const float*)d_in[13];
    const float* W1   = (const float*)d_in[14];
    const float* b1   = (const float*)d_in[15];
    const float* W2   = (const float*)d_in[16];
    const float* b2   = (const float*)d_in[17];
    const float* W3   = (const float*)d_in[18];
    const float* b3   = (const float*)d_in[19];
    float* out = (float*)d_out;

    static int smem_set = 0;
    if (!smem_set){
        cudaFuncSetAttribute(scores_mma_kernel,
                             cudaFuncAttributeMaxDynamicSharedMemorySize, SMEM_TOTAL);
        smem_set = 1;
    }

    conv_ua<<<(NB*(KP/2)+255)/256, 256>>>(Ua);
    {
        size_t tot = (size_t)BB*TT*KP4;
        conv_enc<<<(unsigned)((tot+255)/256), 256>>>(enc);
    }
    qproj_kernel<<<BB, 256>>>(h0, Wa, ba, bua);
    dim3 g2(TT/BM, BB);
    scores_mma_kernel<<<g2, NTHR, SMEM_TOTAL>>>(Va, bva);
    softmax_kernel<<<BB, 256>>>();
    dim3 g4(BB, NSEG);
    context_part<<<g4, 256>>>(enc);
    context_reduce<<<BB, 256>>>();
    decoder_kernel<<<BB, 256>>>(x, h0, c0, W_ih, W_hh, b_ih, b_hh, W1, b1, W2, b2, W3, b3, out);
}

// round 12
// speedup vs baseline: 2.5047x; 1.1072x over previous
#include <cuda_runtime.h>
#include <cuda_bf16.h>
#include <cstdint>
#include <math.h>

#define BB 128
#define TT 2048
#define HH 200
#define STEPS 5

// ---------------- mma.sync scores-GEMM geometry ----------------
#define BM      128
#define KC      64
#define NCHUNK  4
#define NTHR    512
#define NB      208
#define KP      208
#define KP4     26
#define SROW    144
#define SSTG    96768
#define OFF_AH  0
#define OFF_AL  18432
#define OFF_BH  36864
#define OFF_BL  66816
#define OFF_QB  193536
#define OFF_VA  194336
#define OFF_RED 195136
#define SMEM_TOTAL 196160

#define NSEG 16

__device__ float d_qpb[BB*HH];
__device__ float d_scores[BB*TT];
__device__ float d_attn[BB*TT];
__device__ float d_ctxp[BB*NSEG*HH];
__device__ uint32_t d_EncHi[(size_t)BB*TT*(KP/2)];
__device__ uint32_t d_EncLo[(size_t)BB*TT*(KP/2)];
__device__ uint32_t d_UaHi[NB*(KP/2)];
__device__ uint32_t d_UaLo[NB*(KP/2)];
// transposed weights (coalesced inner loops)
__device__ float d_WihT[HH*4*HH];    // [200][800]
__device__ float d_WhhT[HH*4*HH];    // [200][800]
__device__ float d_WaT[HH*HH];       // [200][200]
__device__ float d_W1T[HH*100];      // [200][100]
__device__ float d_W2T[100*50];      // [100][50]
__device__ float d_w0[4*HH];         // W_ih[:,0]

__device__ __forceinline__ float fast_tanh(float x){
    float e = __expf(2.0f*x);
    return 1.0f - 2.0f/(e+1.0f);
}
__device__ __forceinline__ float sigm(float x){
    return 1.0f/(1.0f+__expf(-x));
}
__device__ __forceinline__ uint32_t smem_u32(const void* p){
    uint32_t a;
    asm("{ .reg .u64 t; cvta.to.shared.u64 t, %1; cvt.u32.u64 %0, t; }" : "=r"(a) : "l"(p));
    return a;
}
__device__ __forceinline__ void ldsm_x4(uint32_t* r, uint32_t addr){
    asm volatile("ldmatrix.sync.aligned.m8n8.x4.shared.b16 {%0,%1,%2,%3}, [%4];"
        : "=r"(r[0]),"=r"(r[1]),"=r"(r[2]),"=r"(r[3]) : "r"(addr));
}
__device__ __forceinline__ void ldsm_x2(uint32_t* r, uint32_t addr){
    asm volatile("ldmatrix.sync.aligned.m8n8.x2.shared.b16 {%0,%1}, [%2];"
        : "=r"(r[0]),"=r"(r[1]) : "r"(addr));
}
__device__ __forceinline__ void mma_bf16(float* c, const uint32_t* a, const uint32_t* b){
    asm volatile("mma.sync.aligned.m16n8k16.row.col.f32.bf16.bf16.f32 "
        "{%0,%1,%2,%3}, {%4,%5,%6,%7}, {%8,%9}, {%0,%1,%2,%3};"
        : "+f"(c[0]),"+f"(c[1]),"+f"(c[2]),"+f"(c[3])
        : "r"(a[0]),"r"(a[1]),"r"(a[2]),"r"(a[3]), "r"(b[0]),"r"(b[1]));
}
__device__ __forceinline__ void split1(float v, uint32_t& hi16, uint32_t& lo16){
    __nv_bfloat16 hb = __float2bfloat16_rn(v);
    __nv_bfloat16 lb = __float2bfloat16_rn(v - __bfloat162float(hb));
    hi16 = __bfloat16_as_ushort(hb);
    lo16 = __bfloat16_as_ushort(lb);
}
__device__ __forceinline__ void cpa16(uint32_t dst, const void* src){
    asm volatile("cp.async.ca.shared.global [%0], [%1], 16;" :: "r"(dst), "l"(src));
}
#define CP_COMMIT()  asm volatile("cp.async.commit_group;" ::: "memory")
#define CP_WAIT(n)   asm volatile("cp.async.wait_group %0;" :: "n"(n) : "memory")

// -------------------- K0a: Ua -> bf16 hi/lo padded
__global__ void conv_ua(const float* __restrict__ Ua){
    int idx = blockIdx.x*blockDim.x + threadIdx.x;
    if (idx < NB*(KP/2)){
        int n = idx / (KP/2), kq = idx % (KP/2);
        int gk = kq*2;
        float2 v = make_float2(0.f, 0.f);
        if (n < HH && gk < HH) v = *reinterpret_cast<const float2*>(Ua + (size_t)n*HH + gk);
        uint32_t h0,l0,h1,l1;
        split1(v.x,h0,l0); split1(v.y,h1,l1);
        d_UaHi[idx] = (h1<<16)|h0; d_UaLo[idx] = (l1<<16)|l0;
    }
}
// -------------------- K0b: enc -> bf16 hi/lo padded, uint4-vectorized
__global__ void conv_enc(const float* __restrict__ enc){
    size_t idx = (size_t)blockIdx.x*blockDim.x + threadIdx.x;
    if (idx >= (size_t)BB*TT*KP4) return;
    size_t row = idx / KP4;
    int q4 = (int)(idx % KP4);
    int gk = q4*8;
    float v[8];
    const float* base = enc + row*HH + gk;
    #pragma unroll
    for (int i=0;i<8;i++) v[i] = (gk+i < HH) ? base[i] : 0.f;
    uint32_t hi[8], lo[8];
    #pragma unroll
    for (int i=0;i<8;i++) split1(v[i], hi[i], lo[i]);
    uint4 H, L;
    H.x=(hi[1]<<16)|hi[0]; H.y=(hi[3]<<16)|hi[2]; H.z=(hi[5]<<16)|hi[4]; H.w=(hi[7]<<16)|hi[6];
    L.x=(lo[1]<<16)|lo[0]; L.y=(lo[3]<<16)|lo[2]; L.z=(lo[5]<<16)|lo[4]; L.w=(lo[7]<<16)|lo[6];
    reinterpret_cast<uint4*>(d_EncHi)[idx] = H;
    reinterpret_cast<uint4*>(d_EncLo)[idx] = L;
}
// -------------------- K0c: weight transposes (one-time, tiny)
__global__ void conv_w(const float* __restrict__ Wa, const float* __restrict__ W_ih,
                       const float* __restrict__ W_hh, const float* __restrict__ W1,
                       const float* __restrict__ W2){
    int i = blockIdx.x*blockDim.x + threadIdx.x;
    if (i < HH*4*HH){                       // 160000: WihT + WhhT
        int k = i / (4*HH), j = i % (4*HH);
        d_WihT[i] = W_ih[(size_t)j*(HH+1) + 1 + k];
        d_WhhT[i] = W_hh[(size_t)j*HH + k];
    }
    if (i < HH*HH){                         // 40000: WaT[k][h] = Wa[h][k]
        int k = i / HH, h = i % HH;
        d_WaT[i] = Wa[h*HH + k];
    }
    if (i < HH*100){                        // 20000: W1T[k][j] = W1[j][k]
        int k = i / 100, j = i % 100;
        d_W1T[i] = W1[j*HH + k];
    }
    if (i < 100*50){                        // 5000: W2T[k][j] = W2[j][k]
        int k = i / 50, j = i % 50;
        d_W2T[i] = W2[j*100 + k];
    }
    if (i < 4*HH) d_w0[i] = W_ih[(size_t)i*(HH+1)];
}

// ------------------------------------------------- K1: qpb = h0@Wa.T+ba+bua (coalesced WaT)
__global__ void qproj_kernel(const float* __restrict__ h0,
                             const float* __restrict__ ba, const float* __restrict__ bua){
    int b = blockIdx.x;
    __shared__ float qS[HH];
    for (int k = threadIdx.x; k < HH; k += blockDim.x) qS[k] = h0[b*HH + k];
    __syncthreads();
    int h = threadIdx.x;
    if (h < HH){
        float s = ba[h] + bua[h];
        #pragma unroll 4
        for (int k = 0; k < HH; k++) s += qS[k]*d_WaT[k*HH + h];
        d_qpb[b*HH + h] = s;
    }
}

// ---- K2: double-buffered cp.async pipeline + mma.sync bf16 hi/lo (at legacy-HMMA roofline)
__global__ void __launch_bounds__(NTHR)
scores_mma_kernel(const float* __restrict__ Va, const float* __restrict__ bva){
    extern __shared__ char sm[];
    uint32_t smb = smem_u32(sm);
    int tid  = threadIdx.x;
    int lane = tid & 31;
    int wid  = tid >> 5;
    int half = wid >> 3;
    int m0   = (wid & 7) * 16;
    int tile0 = half ? 13 : 0;
    int b  = blockIdx.y;
    int t0 = blockIdx.x * BM;
    size_t rowA0 = (size_t)(b*TT + t0);

    float* qbS = (float*)(sm + OFF_QB);
    float* vaS = (float*)(sm + OFF_VA);
    float* red = (float*)(sm + OFF_RED);
    for (int h = tid; h < HH; h += NTHR){ qbS[h] = d_qpb[b*HH + h]; vaS[h] = Va[h]; }

    float c[13][4];
    #pragma unroll
    for (int i=0;i<13;i++){ c[i][0]=0.f; c[i][1]=0.f; c[i][2]=0.f; c[i][3]=0.f; }

    const uint4* encHi4 = reinterpret_cast<const uint4*>(d_EncHi);
    const uint4* encLo4 = reinterpret_cast<const uint4*>(d_EncLo);
    const uint4* uaHi4  = reinterpret_cast<const uint4*>(d_UaHi);
    const uint4* uaLo4  = reinterpret_cast<const uint4*>(d_UaLo);

    int aRow = m0 + (lane & 15);
    int aKof = ((lane >> 4) & 1) * 16;
    int bPairTileOff = (lane >> 4);
    int bPairKof  = ((lane >> 3) & 1) * 16;
    int bPairRow  = lane & 7;
    int bRowL = lane & 7;
    int bKofL = ((lane >> 3) & 1) * 16;

    auto load_chunk = [&](int ch, int stg){
        uint32_t sb = smb + stg*SSTG;
        int jmax = (ch < 3) ? 8 : 2;
        for (int i = tid; i < BM*jmax; i += NTHR){
            int t = i / jmax, j = i % jmax;
            cpa16(sb + OFF_AH + t*SROW + j*16, encHi4 + (rowA0 + t)*KP4 + ch*8 + j);
            cpa16(sb + OFF_AL + t*SROW + j*16, encLo4 + (rowA0 + t)*KP4 + ch*8 + j);
        }
        for (int i = tid; i < NB*jmax; i += NTHR){
            int n = i / jmax, j = i % jmax;
            cpa16(sb + OFF_BH + n*SROW + j*16, uaHi4 + n*KP4 + ch*8 + j);
            cpa16(sb + OFF_BL + n*SROW + j*16, uaLo4 + n*KP4 + ch*8 + j);
        }
    };

    load_chunk(0, 0);
    CP_COMMIT();

    for (int ch = 0; ch < NCHUNK; ch++){
        if (ch < NCHUNK-1){ load_chunk(ch+1, (ch+1)&1); CP_COMMIT(); }
        if (ch < NCHUNK-1) CP_WAIT(1); else CP_WAIT(0);
        __syncthreads();

        uint32_t sb = smb + (ch&1)*SSTG;
        int nkt = (ch < 3) ? 4 : 1;
        for (int ks = 0; ks < nkt; ks++){
            uint32_t aHi[4], aLo[4];
            uint32_t aoff = (uint32_t)(aRow*SROW + ks*32 + aKof);
            ldsm_x4(aHi, sb + OFF_AH + aoff);
            ldsm_x4(aLo, sb + OFF_AL + aoff);
            #pragma unroll
            for (int p = 0; p < 6; p++){
                uint32_t bHi[4], bLo[4];
                uint32_t boff = (uint32_t)((((tile0 + 2*p + bPairTileOff)*8) + bPairRow)*SROW
                                           + ks*32 + bPairKof);
                ldsm_x4(bHi, sb + OFF_BH + boff);
                ldsm_x4(bLo, sb + OFF_BL + boff);
                mma_bf16(c[2*p],   aHi, bHi);
                mma_bf16(c[2*p],   aHi, bLo);
                mma_bf16(c[2*p],   aLo, bHi);
                mma_bf16(c[2*p+1], aHi, bHi+2);
                mma_bf16(c[2*p+1], aHi, bLo+2);
                mma_bf16(c[2*p+1], aLo, bHi+2);
            }
            {
                uint32_t bHi[2], bLo[2];
                uint32_t boff = (uint32_t)(((tile0+12)*8 + bRowL)*SROW + ks*32 + bKofL);
                ldsm_x2(bHi, sb + OFF_BH + boff);
                ldsm_x2(bLo, sb + OFF_BL + boff);
                mma_bf16(c[12], aHi, bHi);
                mma_bf16(c[12], aHi, bLo);
                mma_bf16(c[12], aLo, bHi);
            }
        }
        __syncthreads();
    }

    float s0 = 0.f, s1 = 0.f;
    #pragma unroll
    for (int nt = 0; nt < 13; nt++){
        int h0 = (tile0+nt)*8 + (lane & 3)*2;
        if (h0 < HH){
            s0 += vaS[h0]  * fast_tanh(qbS[h0]  + c[nt][0]);
            s0 += vaS[h0+1]* fast_tanh(qbS[h0+1]+ c[nt][1]);
            s1 += vaS[h0]  * fast_tanh(qbS[h0]  + c[nt][2]);
            s1 += vaS[h0+1]* fast_tanh(qbS[h0+1]+ c[nt][3]);
        }
    }
    s0 += __shfl_xor_sync(0xFFFFFFFFu, s0, 1);
    s0 += __shfl_xor_sync(0xFFFFFFFFu, s0, 2);
    s1 += __shfl_xor_sync(0xFFFFFFFFu, s1, 1);
    s1 += __shfl_xor_sync(0xFFFFFFFFu, s1, 2);
    if ((lane & 3) == 0){
        int r0 = m0 + (lane >> 2);
        red[r0*2 + half]     = s0;
        red[(r0+8)*2 + half] = s1;
    }
    __syncthreads();
    if (tid < BM){
        d_scores[(size_t)b*TT + t0 + tid] = red[tid*2] + red[tid*2+1] + bva[0];
    }
}

// ---------------------------------------------------------- K3: softmax over T
__global__ void softmax_kernel(){
    int b = blockIdx.x;
    int tid = threadIdx.x;
    __shared__ float red[256];
    float v[8];
    float m = -1e30f;
    #pragma unroll
    for (int i=0;i<8;i++){ v[i] = d_scores[(size_t)b*TT + tid + i*256]; m = fmaxf(m, v[i]); }
    red[tid] = m; __syncthreads();
    for (int s=128; s>0; s>>=1){ if (tid<s) red[tid]=fmaxf(red[tid],red[tid+s]); __syncthreads(); }
    m = red[0]; __syncthreads();
    float sum=0.f;
    #pragma unroll
    for (int i=0;i<8;i++){ v[i]=__expf(v[i]-m); sum+=v[i]; }
    red[tid]=sum; __syncthreads();
    for (int s=128;s>0;s>>=1){ if(tid<s) red[tid]+=red[tid+s]; __syncthreads(); }
    float inv = 1.0f/red[0];
    #pragma unroll
    for (int i=0;i<8;i++) d_attn[(size_t)b*TT + tid + i*256] = v[i]*inv;
}

// -------------------- K4: partial context over t-segments (grid BB x NSEG)
__global__ void context_part(const float* __restrict__ enc){
    int b = blockIdx.x, seg = blockIdx.y;
    const int TS = TT/NSEG;
    __shared__ float attnS[TS];
    int t00 = seg*TS;
    if (threadIdx.x < TS) attnS[threadIdx.x] = d_attn[(size_t)b*TT + t00 + threadIdx.x];
    __syncthreads();
    int h = threadIdx.x;
    if (h < HH){
        const float* e = enc + (size_t)b*TT*HH + (size_t)t00*HH + h;
        float a0=0,a1=0,a2=0,a3=0;
        #pragma unroll 4
        for (int t=0;t<TS;t+=4){
            a0 += attnS[t]   * e[(size_t)t*HH];
            a1 += attnS[t+1] * e[(size_t)(t+1)*HH];
            a2 += attnS[t+2] * e[(size_t)(t+2)*HH];
            a3 += attnS[t+3] * e[(size_t)(t+3)*HH];
        }
        d_ctxp[(b*NSEG + seg)*HH + h] = (a0+a1)+(a2+a3);
    }
}

// --------- K5: decoder (ctx reduce folded in; transposed coalesced weights)
__global__ void decoder_kernel(const float* __restrict__ x, const float* __restrict__ h0,
                               const float* __restrict__ c0,
                               const float* __restrict__ b_ih, const float* __restrict__ b_hh,
                               const float* __restrict__ b1,
                               const float* __restrict__ b2,
                               const float* __restrict__ W3, const float* __restrict__ b3,
                               float* __restrict__ out){
    int b = blockIdx.x;
    int tid = threadIdx.x;
    __shared__ float ctxS[HH], h0S[HH], c0S[HH];
    __shared__ float gb[4*HH], w0S[4*HH];
    __shared__ float hbuf[HH], o1[100], o2[50];
    __shared__ float xs;
    for (int k=tid;k<HH;k+=blockDim.x){
        float s = 0.f;
        #pragma unroll
        for (int i=0;i<NSEG;i++) s += d_ctxp[(b*NSEG + i)*HH + k];
        ctxS[k]=s; h0S[k]=h0[b*HH+k]; c0S[k]=c0[b*HH+k];
    }
    for (int j=tid;j<4*HH;j+=blockDim.x) w0S[j] = d_w0[j];
    if (tid==0) xs = x[b];
    __syncthreads();
    // gate_base: coalesced WihT/WhhT reads
    for (int j=tid; j<4*HH; j+=blockDim.x){
        float s = b_ih[j] + b_hh[j];
        #pragma unroll 4
        for (int k=0;k<HH;k++) s += ctxS[k]*d_WihT[k*4*HH + j] + h0S[k]*d_WhhT[k*4*HH + j];
        gb[j] = s;
    }
    __syncthreads();
    for (int st=0; st<STEPS; st++){
        float xv = xs;
        if (tid < HH){
            float ig = gb[tid]      + xv*w0S[tid];
            float fg = gb[HH+tid]   + xv*w0S[HH+tid];
            float gg = gb[2*HH+tid] + xv*w0S[2*HH+tid];
            float og = gb[3*HH+tid] + xv*w0S[3*HH+tid];
            float c  = sigm(fg)*c0S[tid] + sigm(ig)*fast_tanh(gg);
            float hn = sigm(og)*fast_tanh(c);
            hbuf[tid] = fmaxf(hn, 0.0f);
        }
        __syncthreads();
        if (tid < 100){
            float s1 = b1[tid];
            #pragma unroll 4
            for (int k=0;k<HH;k++) s1 += d_W1T[k*100 + tid]*hbuf[k];
            o1[tid] = fmaxf(s1, 0.0f);
        }
        __syncthreads();
        if (tid < 50){
            float s2 = b2[tid];
            #pragma unroll 4
            for (int k=0;k<100;k++) s2 += d_W2T[k*50 + tid]*o1[k];
            o2[tid] = fmaxf(s2, 0.0f);
        }
        __syncthreads();
        if (tid == 0){
            float y = b3[0];
            #pragma unroll
            for (int k=0;k<50;k++) y += W3[k]*o2[k];
            out[b*STEPS + st] = y;
            xs = y;
        }
        __syncthreads();
    }
}

extern "C" void kernel_launch(void* const* d_in, const int* in_sizes, int n_in,
                              void* d_out, int out_size){
    const float* x    = (const float*)d_in[0];
    const float* h0   = (const float*)d_in[1];
    const float* c0   = (const float*)d_in[2];
    const float* enc  = (const float*)d_in[3];
    const float* Wa   = (const float*)d_in[4];
    const float* ba   = (const float*)d_in[5];
    const float* Ua   = (const float*)d_in[6];
    const float* bua  = (const float*)d_in[7];
    const float* Va   = (const float*)d_in[8];
    const float* bva  = (const float*)d_in[9];
    const float* W_ih = (const float*)d_in[10];
    const float* W_hh = (const float*)d_in[11];
    const float* b_ih = (const float*)d_in[12];
    const float* b_hh = (const float*)d_in[13];
    const float* W1   = (const float*)d_in[14];
    const float* b1   = (const float*)d_in[15];
    const float* W2   = (const float*)d_in[16];
    const float* b2   = (const float*)d_in[17];
    const float* W3   = (const float*)d_in[18];
    const float* b3   = (const float*)d_in[19];
    float* out = (float*)d_out;

    static int smem_set = 0;
    if (!smem_set){
        cudaFuncSetAttribute(scores_mma_kernel,
                             cudaFuncAttributeMaxDynamicSharedMemorySize, SMEM_TOTAL);
        smem_set = 1;
    }

    conv_ua<<<(NB*(KP/2)+255)/256, 256>>>(Ua);
    conv_w<<<(HH*4*HH+255)/256, 256>>>(Wa, W_ih, W_hh, W1, W2);
    {
        size_t tot = (size_t)BB*TT*KP4;
        conv_enc<<<(unsigned)((tot+255)/256), 256>>>(enc);
    }
    qproj_kernel<<<BB, 256>>>(h0, ba, bua);
    dim3 g2(TT/BM, BB);
    scores_mma_kernel<<<g2, NTHR, SMEM_TOTAL>>>(Va, bva);
    softmax_kernel<<<BB, 256>>>();
    dim3 g4(BB, NSEG);
    context_part<<<g4, 256>>>(enc);
    decoder_kernel<<<BB, 256>>>(x, h0, c0, b_ih, b_hh, b1, b2, W3, b3, out);
}

// round 13
// speedup vs baseline: 2.5240x; 1.0077x over previous
#include <cuda_runtime.h>
#include <cuda_bf16.h>
#include <cstdint>
#include <math.h>

#define BB 128
#define TT 2048
#define HH 200
#define STEPS 5

// ---------------- mma.sync scores-GEMM geometry ----------------
#define BM      128
#define KC      64
#define NCHUNK  4
#define NTHR    512
#define NB      208
#define SROW    144
#define OFF_AH  0
#define OFF_AL  18432
#define OFF_BH  36864
#define OFF_BL  66816
#define OFF_QB  96768
#define OFF_VA  97568
#define OFF_RED 98368
#define SMEM_TOTAL 99392

#define NSEG 16

__device__ float d_qpb[BB*HH];
__device__ float d_scores[BB*TT];
__device__ float d_attn[BB*TT];
__device__ float d_ctxp[BB*NSEG*HH];
__device__ uint32_t d_UaHi[NB*(KC*NCHUNK/2)];   // [208][128] packed pairs (k padded 256)
__device__ uint32_t d_UaLo[NB*(KC*NCHUNK/2)];
// transposed weights (coalesced inner loops)
__device__ float d_WihT[HH*4*HH];
__device__ float d_WhhT[HH*4*HH];
__device__ float d_W1T[HH*100];
__device__ float d_W2T[100*50];
__device__ float d_w0[4*HH];

__device__ __forceinline__ float fast_tanh(float x){
    float e = __expf(2.0f*x);
    return 1.0f - 2.0f/(e+1.0f);
}
__device__ __forceinline__ float sigm(float x){
    return 1.0f/(1.0f+__expf(-x));
}
__device__ __forceinline__ uint32_t smem_u32(const void* p){
    uint32_t a;
    asm("{ .reg .u64 t; cvta.to.shared.u64 t, %1; cvt.u32.u64 %0, t; }" : "=r"(a) : "l"(p));
    return a;
}
__device__ __forceinline__ void ldsm_x4(uint32_t* r, uint32_t addr){
    asm volatile("ldmatrix.sync.aligned.m8n8.x4.shared.b16 {%0,%1,%2,%3}, [%4];"
        : "=r"(r[0]),"=r"(r[1]),"=r"(r[2]),"=r"(r[3]) : "r"(addr));
}
__device__ __forceinline__ void ldsm_x2(uint32_t* r, uint32_t addr){
    asm volatile("ldmatrix.sync.aligned.m8n8.x2.shared.b16 {%0,%1}, [%2];"
        : "=r"(r[0]),"=r"(r[1]) : "r"(addr));
}
__device__ __forceinline__ void mma_bf16(float* c, const uint32_t* a, const uint32_t* b){
    asm volatile("mma.sync.aligned.m16n8k16.row.col.f32.bf16.bf16.f32 "
        "{%0,%1,%2,%3}, {%4,%5,%6,%7}, {%8,%9}, {%0,%1,%2,%3};"
        : "+f"(c[0]),"+f"(c[1]),"+f"(c[2]),"+f"(c[3])
        : "r"(a[0]),"r"(a[1]),"r"(a[2]),"r"(a[3]), "r"(b[0]),"r"(b[1]));
}
__device__ __forceinline__ void split1(float v, uint32_t& hi16, uint32_t& lo16){
    __nv_bfloat16 hb = __float2bfloat16_rn(v);
    __nv_bfloat16 lb = __float2bfloat16_rn(v - __bfloat162float(hb));
    hi16 = __bfloat16_as_ushort(hb);
    lo16 = __bfloat16_as_ushort(lb);
}
__device__ __forceinline__ void split2(float2 v, uint32_t& hi, uint32_t& lo){
    uint32_t h0,l0,h1,l1;
    split1(v.x,h0,l0); split1(v.y,h1,l1);
    hi = (h1<<16)|h0; lo = (l1<<16)|l0;
}
__device__ __forceinline__ void cpa16(uint32_t dst, const void* src){
    asm volatile("cp.async.ca.shared.global [%0], [%1], 16;" :: "r"(dst), "l"(src));
}
#define CP_COMMIT()  asm volatile("cp.async.commit_group;" ::: "memory")
#define CP_WAIT(n)   asm volatile("cp.async.wait_group %0;" :: "n"(n) : "memory")

// -------------------- K0a: Ua -> bf16 hi/lo, [208 n][256 k] pairs
__global__ void conv_ua(const float* __restrict__ Ua){
    int idx = blockIdx.x*blockDim.x + threadIdx.x;   // over NB*128
    if (idx < NB*128){
        int n = idx >> 7, kq = idx & 127;
        int gk = kq*2;
        float2 v = make_float2(0.f, 0.f);
        if (n < HH && gk+1 < HH) v = *reinterpret_cast<const float2*>(Ua + (size_t)n*HH + gk);
        else if (n < HH && gk < HH) v.x = Ua[(size_t)n*HH + gk];
        uint32_t hi, lo; split2(v, hi, lo);
        d_UaHi[idx] = hi; d_UaLo[idx] = lo;
    }
}
// -------------------- K0b: weight transposes (one-time, tiny)
__global__ void conv_w(const float* __restrict__ W_ih,
                       const float* __restrict__ W_hh, const float* __restrict__ W1,
                       const float* __restrict__ W2){
    int i = blockIdx.x*blockDim.x + threadIdx.x;
    if (i < HH*4*HH){
        int k = i / (4*HH), j = i % (4*HH);
        d_WihT[i] = W_ih[(size_t)j*(HH+1) + 1 + k];
        d_WhhT[i] = W_hh[(size_t)j*HH + k];
    }
    if (i < HH*100){
        int k = i / 100, j = i % 100;
        d_W1T[i] = W1[j*HH + k];
    }
    if (i < 100*50){
        int k = i / 50, j = i % 50;
        d_W2T[i] = W2[j*100 + k];
    }
    if (i < 4*HH) d_w0[i] = W_ih[(size_t)i*(HH+1)];
}

// ---------------- K1: qpb = h0@Wa.T+ba+bua — warp per (b,h), lane-parallel k
__global__ void qproj_kernel(const float* __restrict__ h0, const float* __restrict__ Wa,
                             const float* __restrict__ ba, const float* __restrict__ bua){
    int w = blockIdx.x*(blockDim.x>>5) + (threadIdx.x>>5);   // global warp id
    int lane = threadIdx.x & 31;
    if (w >= BB*HH) return;
    int b = w / HH, h = w % HH;
    const float* q  = h0 + b*HH;
    const float* wa = Wa + (size_t)h*HH;
    float s = 0.f;
    #pragma unroll
    for (int k = lane; k < HH; k += 32) s += q[k]*wa[k];
    #pragma unroll
    for (int off = 16; off > 0; off >>= 1) s += __shfl_xor_sync(0xFFFFFFFFu, s, off);
    if (lane == 0) d_qpb[w] = s + ba[h] + bua[h];
}

// ---- K2: in-kernel fp32->bf16 hi/lo convert + mma.sync (at legacy-HMMA roofline)
__global__ void __launch_bounds__(NTHR)
scores_mma_kernel(const float* __restrict__ enc,
                  const float* __restrict__ Va, const float* __restrict__ bva){
    extern __shared__ char sm[];
    uint32_t smb = smem_u32(sm);
    int tid  = threadIdx.x;
    int lane = tid & 31;
    int wid  = tid >> 5;
    int half = wid >> 3;
    int m0   = (wid & 7) * 16;
    int tile0 = half ? 13 : 0;
    int b  = blockIdx.y;
    int t0 = blockIdx.x * BM;

    float* qbS = (float*)(sm + OFF_QB);
    float* vaS = (float*)(sm + OFF_VA);
    float* red = (float*)(sm + OFF_RED);
    for (int h = tid; h < HH; h += NTHR){ qbS[h] = d_qpb[b*HH + h]; vaS[h] = Va[h]; }

    float c[13][4];
    #pragma unroll
    for (int i=0;i<13;i++){ c[i][0]=0.f; c[i][1]=0.f; c[i][2]=0.f; c[i][3]=0.f; }

    const float* encB = enc + ((size_t)(b*TT + t0))*HH;

    int aRow = m0 + (lane & 15);
    int aKof = ((lane >> 4) & 1) * 16;
    int bPairTileOff = (lane >> 4);
    int bPairKof  = ((lane >> 3) & 1) * 16;
    int bPairRow  = lane & 7;
    int bRowL = lane & 7;
    int bKofL = ((lane >> 3) & 1) * 16;

    for (int ch = 0; ch < NCHUNK; ch++){
        __syncthreads();   // previous chunk's LDSMs done
        // A: convert Enc rows on the fly (hidden under HMMA roofline — r8 evidence)
        for (int i = tid; i < BM*32; i += NTHR){
            int t = i >> 5, kp = i & 31;
            int gk = ch*KC + kp*2;
            float2 v = make_float2(0.f, 0.f);
            if (gk+1 < HH) v = *reinterpret_cast<const float2*>(encB + (size_t)t*HH + gk);
            uint32_t hi, lo; split2(v, hi, lo);
            *(uint32_t*)(sm + OFF_AH + t*SROW + kp*4) = hi;
            *(uint32_t*)(sm + OFF_AL + t*SROW + kp*4) = lo;
        }
        // B: copy precomputed Ua hi/lo (cp.async, 16B)
        {
            int jmax = (ch < 3) ? 8 : 2;
            const uint4* uaHi4 = reinterpret_cast<const uint4*>(d_UaHi);
            const uint4* uaLo4 = reinterpret_cast<const uint4*>(d_UaLo);
            for (int i = tid; i < NB*jmax; i += NTHR){
                int n = i / jmax, j = i % jmax;
                cpa16(smb + OFF_BH + n*SROW + j*16, uaHi4 + n*32 + ch*8 + j);
                cpa16(smb + OFF_BL + n*SROW + j*16, uaLo4 + n*32 + ch*8 + j);
            }
            CP_COMMIT();
            CP_WAIT(0);
        }
        __syncthreads();

        int nkt = (ch < 3) ? 4 : 1;
        for (int ks = 0; ks < nkt; ks++){
            uint32_t aHi[4], aLo[4];
            uint32_t aoff = (uint32_t)(aRow*SROW + ks*32 + aKof);
            ldsm_x4(aHi, smb + OFF_AH + aoff);
            ldsm_x4(aLo, smb + OFF_AL + aoff);
            #pragma unroll
            for (int p = 0; p < 6; p++){
                uint32_t bHi[4], bLo[4];
                uint32_t boff = (uint32_t)((((tile0 + 2*p + bPairTileOff)*8) + bPairRow)*SROW
                                           + ks*32 + bPairKof);
                ldsm_x4(bHi, smb + OFF_BH + boff);
                ldsm_x4(bLo, smb + OFF_BL + boff);
                mma_bf16(c[2*p],   aHi, bHi);
                mma_bf16(c[2*p],   aHi, bLo);
                mma_bf16(c[2*p],   aLo, bHi);
                mma_bf16(c[2*p+1], aHi, bHi+2);
                mma_bf16(c[2*p+1], aHi, bLo+2);
                mma_bf16(c[2*p+1], aLo, bHi+2);
            }
            {
                uint32_t bHi[2], bLo[2];
                uint32_t boff = (uint32_t)(((tile0+12)*8 + bRowL)*SROW + ks*32 + bKofL);
                ldsm_x2(bHi, smb + OFF_BH + boff);
                ldsm_x2(bLo, smb + OFF_BL + boff);
                mma_bf16(c[12], aHi, bHi);
                mma_bf16(c[12], aHi, bLo);
                mma_bf16(c[12], aLo, bHi);
            }
        }
    }

    float s0 = 0.f, s1 = 0.f;
    #pragma unroll
    for (int nt = 0; nt < 13; nt++){
        int h0 = (tile0+nt)*8 + (lane & 3)*2;
        if (h0 < HH){
            s0 += vaS[h0]  * fast_tanh(qbS[h0]  + c[nt][0]);
            s0 += vaS[h0+1]* fast_tanh(qbS[h0+1]+ c[nt][1]);
            s1 += vaS[h0]  * fast_tanh(qbS[h0]  + c[nt][2]);
            s1 += vaS[h0+1]* fast_tanh(qbS[h0+1]+ c[nt][3]);
        }
    }
    s0 += __shfl_xor_sync(0xFFFFFFFFu, s0, 1);
    s0 += __shfl_xor_sync(0xFFFFFFFFu, s0, 2);
    s1 += __shfl_xor_sync(0xFFFFFFFFu, s1, 1);
    s1 += __shfl_xor_sync(0xFFFFFFFFu, s1, 2);
    if ((lane & 3) == 0){
        int r0 = m0 + (lane >> 2);
        red[r0*2 + half]     = s0;
        red[(r0+8)*2 + half] = s1;
    }
    __syncthreads();
    if (tid < BM){
        d_scores[(size_t)b*TT + t0 + tid] = red[tid*2] + red[tid*2+1] + bva[0];
    }
}

// ---------------------------------------------------------- K3: softmax over T
__global__ void softmax_kernel(){
    int b = blockIdx.x;
    int tid = threadIdx.x;
    __shared__ float red[256];
    float v[8];
    float m = -1e30f;
    #pragma unroll
    for (int i=0;i<8;i++){ v[i] = d_scores[(size_t)b*TT + tid + i*256]; m = fmaxf(m, v[i]); }
    red[tid] = m; __syncthreads();
    for (int s=128; s>0; s>>=1){ if (tid<s) red[tid]=fmaxf(red[tid],red[tid+s]); __syncthreads(); }
    m = red[0]; __syncthreads();
    float sum=0.f;
    #pragma unroll
    for (int i=0;i<8;i++){ v[i]=__expf(v[i]-m); sum+=v[i]; }
    red[tid]=sum; __syncthreads();
    for (int s=128;s>0;s>>=1){ if(tid<s) red[tid]+=red[tid+s]; __syncthreads(); }
    float inv = 1.0f/red[0];
    #pragma unroll
    for (int i=0;i<8;i++) d_attn[(size_t)b*TT + tid + i*256] = v[i]*inv;
}

// -------------------- K4: partial context over t-segments (grid BB x NSEG)
__global__ void context_part(const float* __restrict__ enc){
    int b = blockIdx.x, seg = blockIdx.y;
    const int TS = TT/NSEG;
    __shared__ float attnS[TS];
    int t00 = seg*TS;
    if (threadIdx.x < TS) attnS[threadIdx.x] = d_attn[(size_t)b*TT + t00 + threadIdx.x];
    __syncthreads();
    int h = threadIdx.x;
    if (h < HH){
        const float* e = enc + (size_t)b*TT*HH + (size_t)t00*HH + h;
        float a0=0,a1=0,a2=0,a3=0;
        #pragma unroll 4
        for (int t=0;t<TS;t+=4){
            a0 += attnS[t]   * e[(size_t)t*HH];
            a1 += attnS[t+1] * e[(size_t)(t+1)*HH];
            a2 += attnS[t+2] * e[(size_t)(t+2)*HH];
            a3 += attnS[t+3] * e[(size_t)(t+3)*HH];
        }
        d_ctxp[(b*NSEG + seg)*HH + h] = (a0+a1)+(a2+a3);
    }
}

// --------- K5: decoder (ctx reduce folded in; transposed coalesced weights)
__global__ void decoder_kernel(const float* __restrict__ x, const float* __restrict__ h0,
                               const float* __restrict__ c0,
                               const float* __restrict__ b_ih, const float* __restrict__ b_hh,
                               const float* __restrict__ b1,
                               const float* __restrict__ b2,
                               const float* __restrict__ W3, const float* __restrict__ b3,
                               float* __restrict__ out){
    int b = blockIdx.x;
    int tid = threadIdx.x;
    __shared__ float ctxS[HH], h0S[HH], c0S[HH];
    __shared__ float gb[4*HH], w0S[4*HH];
    __shared__ float hbuf[HH], o1[100], o2[50];
    __shared__ float xs;
    for (int k=tid;k<HH;k+=blockDim.x){
        float s = 0.f;
        #pragma unroll
        for (int i=0;i<NSEG;i++) s += d_ctxp[(b*NSEG + i)*HH + k];
        ctxS[k]=s; h0S[k]=h0[b*HH+k]; c0S[k]=c0[b*HH+k];
    }
    for (int j=tid;j<4*HH;j+=blockDim.x) w0S[j] = d_w0[j];
    if (tid==0) xs = x[b];
    __syncthreads();
    for (int j=tid; j<4*HH; j+=blockDim.x){
        float s = b_ih[j] + b_hh[j];
        #pragma unroll 4
        for (int k=0;k<HH;k++) s += ctxS[k]*d_WihT[k*4*HH + j] + h0S[k]*d_WhhT[k*4*HH + j];
        gb[j] = s;
    }
    __syncthreads();
    for (int st=0; st<STEPS; st++){
        float xv = xs;
        if (tid < HH){
            float ig = gb[tid]      + xv*w0S[tid];
            float fg = gb[HH+tid]   + xv*w0S[HH+tid];
            float gg = gb[2*HH+tid] + xv*w0S[2*HH+tid];
            float og = gb[3*HH+tid] + xv*w0S[3*HH+tid];
            float c  = sigm(fg)*c0S[tid] + sigm(ig)*fast_tanh(gg);
            float hn = sigm(og)*fast_tanh(c);
            hbuf[tid] = fmaxf(hn, 0.0f);
        }
        __syncthreads();
        if (tid < 100){
            float s1 = b1[tid];
            #pragma unroll 4
            for (int k=0;k<HH;k++) s1 += d_W1T[k*100 + tid]*hbuf[k];
            o1[tid] = fmaxf(s1, 0.0f);
        }
        __syncthreads();
        if (tid < 50){
            float s2 = b2[tid];
            #pragma unroll 4
            for (int k=0;k<100;k++) s2 += d_W2T[k*50 + tid]*o1[k];
            o2[tid] = fmaxf(s2, 0.0f);
        }
        __syncthreads();
        if (tid == 0){
            float y = b3[0];
            #pragma unroll
            for (int k=0;k<50;k++) y += W3[k]*o2[k];
            out[b*STEPS + st] = y;
            xs = y;
        }
        __syncthreads();
    }
}

extern "C" void kernel_launch(void* const* d_in, const int* in_sizes, int n_in,
                              void* d_out, int out_size){
    const float* x    = (const float*)d_in[0];
    const float* h0   = (const float*)d_in[1];
    const float* c0   = (const float*)d_in[2];
    const float* enc  = (const float*)d_in[3];
    const float* Wa   = (const float*)d_in[4];
    const float* ba   = (const float*)d_in[5];
    const float* Ua   = (const float*)d_in[6];
    const float* bua  = (const float*)d_in[7];
    const float* Va   = (const float*)d_in[8];
    const float* bva  = (const float*)d_in[9];
    const float* W_ih = (const float*)d_in[10];
    const float* W_hh = (const float*)d_in[11];
    const float* b_ih = (const float*)d_in[12];
    const float* b_hh = (const float*)d_in[13];
    const float* W1   = (const float*)d_in[14];
    const float* b1   = (const float*)d_in[15];
    const float* W2   = (const float*)d_in[16];
    const float* b2   = (const float*)d_in[17];
    const float* W3   = (const float*)d_in[18];
    const float* b3   = (const float*)d_in[19];
    float* out = (float*)d_out;

    static int smem_set = 0;
    if (!smem_set){
        cudaFuncSetAttribute(scores_mma_kernel,
                             cudaFuncAttributeMaxDynamicSharedMemorySize, SMEM_TOTAL);
        smem_set = 1;
    }

    conv_ua<<<(NB*128+255)/256, 256>>>(Ua);
    conv_w<<<(HH*4*HH+255)/256, 256>>>(W_ih, W_hh, W1, W2);
    qproj_kernel<<<(BB*HH*32 + 255)/256, 256>>>(h0, Wa, ba, bua);
    dim3 g2(TT/BM, BB);
    scores_mma_kernel<<<g2, NTHR, SMEM_TOTAL>>>(enc, Va, bva);
    softmax_kernel<<<BB, 256>>>();
    dim3 g4(BB, NSEG);
    context_part<<<g4, 256>>>(enc);
    decoder_kernel<<<BB, 256>>>(x, h0, c0, b_ih, b_hh, b1, b2, W3, b3, out);
}

// round 14
// speedup vs baseline: 3.6225x; 1.4352x over previous
#include <cuda_runtime.h>
#include <cuda_bf16.h>
#include <cstdint>
#include <math.h>

#define BB 128
#define TT 2048
#define HH 200
#define STEPS 5

// ---------------- mma.sync scores-GEMM geometry ----------------
#define BM      128
#define KC      64
#define NCHUNK  4
#define NTHR    512
#define NB      208
#define SROW    144
#define OFF_AH  0
#define OFF_AL  18432
#define OFF_BH  36864
#define OFF_BL  66816
#define OFF_QB  96768
#define OFF_VA  97568
#define OFF_RED 98368
#define SMEM_TOTAL 99392

#define NSEG 16

__device__ float d_qpb[BB*HH];
__device__ float d_scores[BB*TT];
__device__ float d_attn[BB*TT];
__device__ float d_ctxp[BB*NSEG*HH];
__device__ float d_gb[BB*4*HH];
__device__ uint32_t d_UaHi[NB*(KC*NCHUNK/2)];   // [208][128] packed bf16 pairs
__device__ uint32_t d_UaLo[NB*(KC*NCHUNK/2)];
__device__ float d_WihT[HH*4*HH];
__device__ float d_WhhT[HH*4*HH];
__device__ float d_W1T[HH*100];
__device__ float d_W2T[100*50];
__device__ float d_w0[4*HH];

__device__ __forceinline__ float fast_tanh(float x){
    float e = __expf(2.0f*x);
    return 1.0f - 2.0f/(e+1.0f);
}
__device__ __forceinline__ float sigm(float x){
    return 1.0f/(1.0f+__expf(-x));
}
__device__ __forceinline__ uint32_t smem_u32(const void* p){
    uint32_t a;
    asm("{ .reg .u64 t; cvta.to.shared.u64 t, %1; cvt.u32.u64 %0, t; }" : "=r"(a) : "l"(p));
    return a;
}
__device__ __forceinline__ void ldsm_x4(uint32_t* r, uint32_t addr){
    asm volatile("ldmatrix.sync.aligned.m8n8.x4.shared.b16 {%0,%1,%2,%3}, [%4];"
        : "=r"(r[0]),"=r"(r[1]),"=r"(r[2]),"=r"(r[3]) : "r"(addr));
}
__device__ __forceinline__ void ldsm_x2(uint32_t* r, uint32_t addr){
    asm volatile("ldmatrix.sync.aligned.m8n8.x2.shared.b16 {%0,%1}, [%2];"
        : "=r"(r[0]),"=r"(r[1]) : "r"(addr));
}
__device__ __forceinline__ void mma_bf16(float* c, const uint32_t* a, const uint32_t* b){
    asm volatile("mma.sync.aligned.m16n8k16.row.col.f32.bf16.bf16.f32 "
        "{%0,%1,%2,%3}, {%4,%5,%6,%7}, {%8,%9}, {%0,%1,%2,%3};"
        : "+f"(c[0]),"+f"(c[1]),"+f"(c[2]),"+f"(c[3])
        : "r"(a[0]),"r"(a[1]),"r"(a[2]),"r"(a[3]), "r"(b[0]),"r"(b[1]));
}
__device__ __forceinline__ void split1(float v, uint32_t& hi16, uint32_t& lo16){
    __nv_bfloat16 hb = __float2bfloat16_rn(v);
    __nv_bfloat16 lb = __float2bfloat16_rn(v - __bfloat162float(hb));
    hi16 = __bfloat16_as_ushort(hb);
    lo16 = __bfloat16_as_ushort(lb);
}
__device__ __forceinline__ void split2(float2 v, uint32_t& hi, uint32_t& lo){
    uint32_t h0,l0,h1,l1;
    split1(v.x,h0,l0); split1(v.y,h1,l1);
    hi = (h1<<16)|h0; lo = (l1<<16)|l0;
}
__device__ __forceinline__ void cpa16(uint32_t dst, const void* src){
    asm volatile("cp.async.ca.shared.global [%0], [%1], 16;" :: "r"(dst), "l"(src));
}
#define CP_COMMIT()  asm volatile("cp.async.commit_group;" ::: "memory")
#define CP_WAIT(n)   asm volatile("cp.async.wait_group %0;" :: "n"(n) : "memory")

// -------------------- K0a: Ua -> bf16 hi/lo, [208 n][256 k] pairs
__global__ void conv_ua(const float* __restrict__ Ua){
    int idx = blockIdx.x*blockDim.x + threadIdx.x;
    if (idx < NB*128){
        int n = idx >> 7, kq = idx & 127;
        int gk = kq*2;
        float2 v = make_float2(0.f, 0.f);
        if (n < HH && gk+1 < HH) v = *reinterpret_cast<const float2*>(Ua + (size_t)n*HH + gk);
        else if (n < HH && gk < HH) v.x = Ua[(size_t)n*HH + gk];
        uint32_t hi, lo; split2(v, hi, lo);
        d_UaHi[idx] = hi; d_UaLo[idx] = lo;
    }
}
// -------------------- K0b: weight transposes (one-time, tiny)
__global__ void conv_w(const float* __restrict__ W_ih,
                       const float* __restrict__ W_hh, const float* __restrict__ W1,
                       const float* __restrict__ W2){
    int i = blockIdx.x*blockDim.x + threadIdx.x;
    if (i < HH*4*HH){
        int k = i / (4*HH), j = i % (4*HH);
        d_WihT[i] = W_ih[(size_t)j*(HH+1) + 1 + k];
        d_WhhT[i] = W_hh[(size_t)j*HH + k];
    }
    if (i < HH*100){
        int k = i / 100, j = i % 100;
        d_W1T[i] = W1[j*HH + k];
    }
    if (i < 100*50){
        int k = i / 50, j = i % 50;
        d_W2T[i] = W2[j*100 + k];
    }
    if (i < 4*HH) d_w0[i] = W_ih[(size_t)i*(HH+1)];
}

// ---------------- K1: qpb = h0@Wa.T+ba+bua — warp per (b,h)
__global__ void qproj_kernel(const float* __restrict__ h0, const float* __restrict__ Wa,
                             const float* __restrict__ ba, const float* __restrict__ bua){
    int w = blockIdx.x*(blockDim.x>>5) + (threadIdx.x>>5);
    int lane = threadIdx.x & 31;
    if (w >= BB*HH) return;
    int b = w / HH, h = w % HH;
    const float* q  = h0 + b*HH;
    const float* wa = Wa + (size_t)h*HH;
    float s = 0.f;
    #pragma unroll
    for (int k = lane; k < HH; k += 32) s += q[k]*wa[k];
    #pragma unroll
    for (int off = 16; off > 0; off >>= 1) s += __shfl_xor_sync(0xFFFFFFFFu, s, off);
    if (lane == 0) d_qpb[w] = s + ba[h] + bua[h];
}

// ---- K2: register-prefetched in-kernel convert + mma.sync bf16 hi/lo
__global__ void __launch_bounds__(NTHR)
scores_mma_kernel(const float* __restrict__ enc,
                  const float* __restrict__ Va, const float* __restrict__ bva){
    extern __shared__ char sm[];
    uint32_t smb = smem_u32(sm);
    int tid  = threadIdx.x;
    int lane = tid & 31;
    int wid  = tid >> 5;
    int half = wid >> 3;
    int m0   = (wid & 7) * 16;
    int tile0 = half ? 13 : 0;
    int b  = blockIdx.y;
    int t0 = blockIdx.x * BM;

    float* qbS = (float*)(sm + OFF_QB);
    float* vaS = (float*)(sm + OFF_VA);
    float* red = (float*)(sm + OFF_RED);
    for (int h = tid; h < HH; h += NTHR){ qbS[h] = d_qpb[b*HH + h]; vaS[h] = Va[h]; }

    float c[13][4];
    #pragma unroll
    for (int i=0;i<13;i++){ c[i][0]=0.f; c[i][1]=0.f; c[i][2]=0.f; c[i][3]=0.f; }

    const float* encB = enc + ((size_t)(b*TT + t0))*HH;

    int aRow = m0 + (lane & 15);
    int aKof = ((lane >> 4) & 1) * 16;
    int bPairTileOff = (lane >> 4);
    int bPairKof  = ((lane >> 3) & 1) * 16;
    int bPairRow  = lane & 7;
    int bRowL = lane & 7;
    int bKofL = ((lane >> 3) & 1) * 16;

    // per-thread A-row mapping: i = tid + r*NTHR, t=i>>5, kp=i&31
    int tA[8], kpA[8];
    #pragma unroll
    for (int r=0;r<8;r++){ int i = tid + r*NTHR; tA[r] = i>>5; kpA[r] = i&31; }

    // prefetch chunk 0 fp32 into registers
    float2 cur[8], nxt[8];
    #pragma unroll
    for (int r=0;r<8;r++){
        int gk = 0*KC + kpA[r]*2;
        cur[r] = (gk+1 < HH) ? *reinterpret_cast<const float2*>(encB + (size_t)tA[r]*HH + gk)
                             : make_float2(0.f, 0.f);
    }

    #pragma unroll
    for (int ch = 0; ch < NCHUNK; ch++){
        __syncthreads();   // previous chunk's LDSMs done -> smem reusable
        // convert prefetched A regs -> smem
        #pragma unroll
        for (int r=0;r<8;r++){
            uint32_t hi, lo; split2(cur[r], hi, lo);
            *(uint32_t*)(sm + OFF_AH + tA[r]*SROW + kpA[r]*4) = hi;
            *(uint32_t*)(sm + OFF_AL + tA[r]*SROW + kpA[r]*4) = lo;
        }
        // B: copy precomputed Ua hi/lo (cp.async 16B)
        {
            int jmax = (ch < 3) ? 8 : 2;
            const uint4* uaHi4 = reinterpret_cast<const uint4*>(d_UaHi);
            const uint4* uaLo4 = reinterpret_cast<const uint4*>(d_UaLo);
            for (int i = tid; i < NB*jmax; i += NTHR){
                int n = i / jmax, j = i % jmax;
                cpa16(smb + OFF_BH + n*SROW + j*16, uaHi4 + n*32 + ch*8 + j);
                cpa16(smb + OFF_BL + n*SROW + j*16, uaLo4 + n*32 + ch*8 + j);
            }
            CP_COMMIT();
            CP_WAIT(0);
        }
        __syncthreads();

        // issue next chunk's LDGs now; they drain under the MMA work below
        if (ch < NCHUNK-1){
            #pragma unroll
            for (int r=0;r<8;r++){
                int gk = (ch+1)*KC + kpA[r]*2;
                nxt[r] = (gk+1 < HH) ? *reinterpret_cast<const float2*>(encB + (size_t)tA[r]*HH + gk)
                                     : make_float2(0.f, 0.f);
            }
        }

        int nkt = (ch < 3) ? 4 : 1;
        for (int ks = 0; ks < nkt; ks++){
            uint32_t aHi[4], aLo[4];
            uint32_t aoff = (uint32_t)(aRow*SROW + ks*32 + aKof);
            ldsm_x4(aHi, smb + OFF_AH + aoff);
            ldsm_x4(aLo, smb + OFF_AL + aoff);
            #pragma unroll
            for (int p = 0; p < 6; p++){
                uint32_t bHi[4], bLo[4];
                uint32_t boff = (uint32_t)((((tile0 + 2*p + bPairTileOff)*8) + bPairRow)*SROW
                                           + ks*32 + bPairKof);
                ldsm_x4(bHi, smb + OFF_BH + boff);
                ldsm_x4(bLo, smb + OFF_BL + boff);
                mma_bf16(c[2*p],   aHi, bHi);
                mma_bf16(c[2*p],   aHi, bLo);
                mma_bf16(c[2*p],   aLo, bHi);
                mma_bf16(c[2*p+1], aHi, bHi+2);
                mma_bf16(c[2*p+1], aHi, bLo+2);
                mma_bf16(c[2*p+1], aLo, bHi+2);
            }
            {
                uint32_t bHi[2], bLo[2];
                uint32_t boff = (uint32_t)(((tile0+12)*8 + bRowL)*SROW + ks*32 + bKofL);
                ldsm_x2(bHi, smb + OFF_BH + boff);
                ldsm_x2(bLo, smb + OFF_BL + boff);
                mma_bf16(c[12], aHi, bHi);
                mma_bf16(c[12], aHi, bLo);
                mma_bf16(c[12], aLo, bHi);
            }
        }
        #pragma unroll
        for (int r=0;r<8;r++) cur[r] = nxt[r];
    }

    float s0 = 0.f, s1 = 0.f;
    #pragma unroll
    for (int nt = 0; nt < 13; nt++){
        int h0 = (tile0+nt)*8 + (lane & 3)*2;
        if (h0 < HH){
            s0 += vaS[h0]  * fast_tanh(qbS[h0]  + c[nt][0]);
            s0 += vaS[h0+1]* fast_tanh(qbS[h0+1]+ c[nt][1]);
            s1 += vaS[h0]  * fast_tanh(qbS[h0]  + c[nt][2]);
            s1 += vaS[h0+1]* fast_tanh(qbS[h0+1]+ c[nt][3]);
        }
    }
    s0 += __shfl_xor_sync(0xFFFFFFFFu, s0, 1);
    s0 += __shfl_xor_sync(0xFFFFFFFFu, s0, 2);
    s1 += __shfl_xor_sync(0xFFFFFFFFu, s1, 1);
    s1 += __shfl_xor_sync(0xFFFFFFFFu, s1, 2);
    if ((lane & 3) == 0){
        int r0 = m0 + (lane >> 2);
        red[r0*2 + half]     = s0;
        red[(r0+8)*2 + half] = s1;
    }
    __syncthreads();
    if (tid < BM){
        d_scores[(size_t)b*TT + t0 + tid] = red[tid*2] + red[tid*2+1] + bva[0];
    }
}

// ---------------------------------------------------------- K3: softmax over T
__global__ void softmax_kernel(){
    int b = blockIdx.x;
    int tid = threadIdx.x;
    __shared__ float red[256];
    float v[8];
    float m = -1e30f;
    #pragma unroll
    for (int i=0;i<8;i++){ v[i] = d_scores[(size_t)b*TT + tid + i*256]; m = fmaxf(m, v[i]); }
    red[tid] = m; __syncthreads();
    for (int s=128; s>0; s>>=1){ if (tid<s) red[tid]=fmaxf(red[tid],red[tid+s]); __syncthreads(); }
    m = red[0]; __syncthreads();
    float sum=0.f;
    #pragma unroll
    for (int i=0;i<8;i++){ v[i]=__expf(v[i]-m); sum+=v[i]; }
    red[tid]=sum; __syncthreads();
    for (int s=128;s>0;s>>=1){ if(tid<s) red[tid]+=red[tid+s]; __syncthreads(); }
    float inv = 1.0f/red[0];
    #pragma unroll
    for (int i=0;i<8;i++) d_attn[(size_t)b*TT + tid + i*256] = v[i]*inv;
}

// -------------------- K4: partial context over t-segments (grid BB x NSEG)
__global__ void context_part(const float* __restrict__ enc){
    int b = blockIdx.x, seg = blockIdx.y;
    const int TS = TT/NSEG;
    __shared__ float attnS[TS];
    int t00 = seg*TS;
    if (threadIdx.x < TS) attnS[threadIdx.x] = d_attn[(size_t)b*TT + t00 + threadIdx.x];
    __syncthreads();
    int h = threadIdx.x;
    if (h < HH){
        const float* e = enc + (size_t)b*TT*HH + (size_t)t00*HH + h;
        float a0=0,a1=0,a2=0,a3=0;
        #pragma unroll 4
        for (int t=0;t<TS;t+=4){
            a0 += attnS[t]   * e[(size_t)t*HH];
            a1 += attnS[t+1] * e[(size_t)(t+1)*HH];
            a2 += attnS[t+2] * e[(size_t)(t+2)*HH];
            a3 += attnS[t+3] * e[(size_t)(t+3)*HH];
        }
        d_ctxp[(b*NSEG + seg)*HH + h] = (a0+a1)+(a2+a3);
    }
}

// -------------------- K4b: gate_base[b,j] (800 threads, one j each, coalesced)
__global__ void gatebase_kernel(const float* __restrict__ h0,
                                const float* __restrict__ b_ih, const float* __restrict__ b_hh){
    int b = blockIdx.x;
    int j = threadIdx.x;                 // 0..799
    __shared__ float ctxS[HH], h0S[HH];
    if (j < HH){
        float s = 0.f;
        #pragma unroll
        for (int i=0;i<NSEG;i++) s += d_ctxp[(b*NSEG + i)*HH + j];
        ctxS[j] = s;
        h0S[j] = h0[b*HH + j];
    }
    __syncthreads();
    float s = b_ih[j] + b_hh[j];
    #pragma unroll 4
    for (int k=0;k<HH;k++) s += ctxS[k]*d_WihT[k*4*HH + j] + h0S[k]*d_WhhT[k*4*HH + j];
    d_gb[b*4*HH + j] = s;
}

// --------- K5: decoder — only the 5 serial steps
__global__ void decoder_kernel(const float* __restrict__ x,
                               const float* __restrict__ c0,
                               const float* __restrict__ b1,
                               const float* __restrict__ b2,
                               const float* __restrict__ W3, const float* __restrict__ b3,
                               float* __restrict__ out){
    int b = blockIdx.x;
    int tid = threadIdx.x;
    __shared__ float c0S[HH];
    __shared__ float gb[4*HH], w0S[4*HH];
    __shared__ float hbuf[HH], o1[100], o2[50];
    __shared__ float xs;
    for (int k=tid;k<HH;k+=blockDim.x) c0S[k]=c0[b*HH+k];
    for (int j=tid;j<4*HH;j+=blockDim.x){ gb[j]=d_gb[b*4*HH+j]; w0S[j]=d_w0[j]; }
    if (tid==0) xs = x[b];
    __syncthreads();
    for (int st=0; st<STEPS; st++){
        float xv = xs;
        if (tid < HH){
            float ig = gb[tid]      + xv*w0S[tid];
            float fg = gb[HH+tid]   + xv*w0S[HH+tid];
            float gg = gb[2*HH+tid] + xv*w0S[2*HH+tid];
            float og = gb[3*HH+tid] + xv*w0S[3*HH+tid];
            float c  = sigm(fg)*c0S[tid] + sigm(ig)*fast_tanh(gg);
            float hn = sigm(og)*fast_tanh(c);
            hbuf[tid] = fmaxf(hn, 0.0f);
        }
        __syncthreads();
        if (tid < 100){
            float s1 = b1[tid];
            #pragma unroll 4
            for (int k=0;k<HH;k++) s1 += d_W1T[k*100 + tid]*hbuf[k];
            o1[tid] = fmaxf(s1, 0.0f);
        }
        __syncthreads();
        if (tid < 50){
            float s2 = b2[tid];
            #pragma unroll 4
            for (int k=0;k<100;k++) s2 += d_W2T[k*50 + tid]*o1[k];
            o2[tid] = fmaxf(s2, 0.0f);
        }
        __syncthreads();
        if (tid == 0){
            float y = b3[0];
            #pragma unroll
            for (int k=0;k<50;k++) y += W3[k]*o2[k];
            out[b*STEPS + st] = y;
            xs = y;
        }
        __syncthreads();
    }
}

extern "C" void kernel_launch(void* const* d_in, const int* in_sizes, int n_in,
                              void* d_out, int out_size){
    const float* x    = (const float*)d_in[0];
    const float* h0   = (const float*)d_in[1];
    const float* c0   = (const float*)d_in[2];
    const float* enc  = (const float*)d_in[3];
    const float* Wa   = (const float*)d_in[4];
    const float* ba   = (const float*)d_in[5];
    const float* Ua   = (const float*)d_in[6];
    const float* bua  = (const float*)d_in[7];
    const float* Va   = (const float*)d_in[8];
    const float* bva  = (const float*)d_in[9];
    const float* W_ih = (const float*)d_in[10];
    const float* W_hh = (const float*)d_in[11];
    const float* b_ih = (const float*)d_in[12];
    const float* b_hh = (const float*)d_in[13];
    const float* W1   = (const float*)d_in[14];
    const float* b1   = (const float*)d_in[15];
    const float* W2   = (const float*)d_in[16];
    const float* b2   = (const float*)d_in[17];
    const float* W3   = (const float*)d_in[18];
    const float* b3   = (const float*)d_in[19];
    float* out = (float*)d_out;

    static int smem_set = 0;
    if (!smem_set){
        cudaFuncSetAttribute(scores_mma_kernel,
                             cudaFuncAttributeMaxDynamicSharedMemorySize, SMEM_TOTAL);
        smem_set = 1;
    }

    conv_ua<<<(NB*128+255)/256, 256>>>(Ua);
    conv_w<<<(HH*4*HH+255)/256, 256>>>(W_ih, W_hh, W1, W2);
    qproj_kernel<<<(BB*HH*32 + 255)/256, 256>>>(h0, Wa, ba, bua);
    dim3 g2(TT/BM, BB);
    scores_mma_kernel<<<g2, NTHR, SMEM_TOTAL>>>(enc, Va, bva);
    softmax_kernel<<<BB, 256>>>();
    dim3 g4(BB, NSEG);
    context_part<<<g4, 256>>>(enc);
    gatebase_kernel<<<BB, 4*HH>>>(h0, b_ih, b_hh);
    decoder_kernel<<<BB, 256>>>(x, c0, b1, b2, W3, b3, out);
}

// round 15
// speedup vs baseline: 3.6757x; 1.0147x over previous
#include <cuda_runtime.h>
#include <cuda_bf16.h>
#include <cstdint>
#include <math.h>

#define BB 128
#define TT 2048
#define HH 200
#define STEPS 5

// ---------------- mma.sync scores-GEMM geometry ----------------
#define BM      128
#define KC      64
#define NCHUNK  4
#define NTHR    512
#define NB      208
#define SROW    144
// smem layout: A single-buffered, B double-buffered
#define OFF_AH   0
#define OFF_AL   18432
#define BSTG     59904              // 208*144*2 per stage
#define OFF_B0H  36864
#define OFF_B0L  66816
#define OFF_B1H  96768
#define OFF_B1L  126720
#define OFF_QB   156672
#define OFF_VA   157472
#define OFF_RED  158272
#define SMEM_TOTAL 159296

#define NSEG 32

__device__ float d_qpb[BB*HH];
__device__ float d_scores[BB*TT];
__device__ float d_smax[BB];
__device__ float d_sinv[BB];
__device__ float d_ctxp[BB*NSEG*HH];
__device__ uint32_t d_UaHi[NB*(KC*NCHUNK/2)];
__device__ uint32_t d_UaLo[NB*(KC*NCHUNK/2)];
__device__ float d_WihT[HH*4*HH];
__device__ float d_WhhT[HH*4*HH];
__device__ float d_W1T[HH*100];
__device__ float d_W2T[100*50];
__device__ float d_w0[4*HH];

__device__ __forceinline__ float fast_tanh(float x){
    float e = __expf(2.0f*x);
    return 1.0f - 2.0f/(e+1.0f);
}
__device__ __forceinline__ float sigm(float x){
    return 1.0f/(1.0f+__expf(-x));
}
__device__ __forceinline__ uint32_t smem_u32(const void* p){
    uint32_t a;
    asm("{ .reg .u64 t; cvta.to.shared.u64 t, %1; cvt.u32.u64 %0, t; }" : "=r"(a) : "l"(p));
    return a;
}
__device__ __forceinline__ void ldsm_x4(uint32_t* r, uint32_t addr){
    asm volatile("ldmatrix.sync.aligned.m8n8.x4.shared.b16 {%0,%1,%2,%3}, [%4];"
        : "=r"(r[0]),"=r"(r[1]),"=r"(r[2]),"=r"(r[3]) : "r"(addr));
}
__device__ __forceinline__ void ldsm_x2(uint32_t* r, uint32_t addr){
    asm volatile("ldmatrix.sync.aligned.m8n8.x2.shared.b16 {%0,%1}, [%2];"
        : "=r"(r[0]),"=r"(r[1]) : "r"(addr));
}
__device__ __forceinline__ void mma_bf16(float* c, const uint32_t* a, const uint32_t* b){
    asm volatile("mma.sync.aligned.m16n8k16.row.col.f32.bf16.bf16.f32 "
        "{%0,%1,%2,%3}, {%4,%5,%6,%7}, {%8,%9}, {%0,%1,%2,%3};"
        : "+f"(c[0]),"+f"(c[1]),"+f"(c[2]),"+f"(c[3])
        : "r"(a[0]),"r"(a[1]),"r"(a[2]),"r"(a[3]), "r"(b[0]),"r"(b[1]));
}
__device__ __forceinline__ void split1(float v, uint32_t& hi16, uint32_t& lo16){
    __nv_bfloat16 hb = __float2bfloat16_rn(v);
    __nv_bfloat16 lb = __float2bfloat16_rn(v - __bfloat162float(hb));
    hi16 = __bfloat16_as_ushort(hb);
    lo16 = __bfloat16_as_ushort(lb);
}
__device__ __forceinline__ void split2(float2 v, uint32_t& hi, uint32_t& lo){
    uint32_t h0,l0,h1,l1;
    split1(v.x,h0,l0); split1(v.y,h1,l1);
    hi = (h1<<16)|h0; lo = (l1<<16)|l0;
}
__device__ __forceinline__ void cpa16(uint32_t dst, const void* src){
    asm volatile("cp.async.ca.shared.global [%0], [%1], 16;" :: "r"(dst), "l"(src));
}
#define CP_COMMIT()  asm volatile("cp.async.commit_group;" ::: "memory")
#define CP_WAIT(n)   asm volatile("cp.async.wait_group %0;" :: "n"(n) : "memory")

// ---------------- K0 (merged prep): conv_w | conv_ua | qproj, partitioned by blockIdx
#define PREP_W_BLKS   625          // 160000/256
#define PREP_UA_BLKS  104          // NB*128/256
#define PREP_Q_BLKS   3200         // BB*HH warps / 8
__global__ void prep_kernel(const float* __restrict__ Ua,
                            const float* __restrict__ W_ih, const float* __restrict__ W_hh,
                            const float* __restrict__ W1, const float* __restrict__ W2,
                            const float* __restrict__ h0, const float* __restrict__ Wa,
                            const float* __restrict__ ba, const float* __restrict__ bua){
    int blk = blockIdx.x;
    if (blk < PREP_W_BLKS){
        int i = blk*256 + threadIdx.x;
        if (i < HH*4*HH){
            int k = i / (4*HH), j = i % (4*HH);
            d_WihT[i] = W_ih[(size_t)j*(HH+1) + 1 + k];
            d_WhhT[i] = W_hh[(size_t)j*HH + k];
        }
        if (i < HH*100){
            int k = i / 100, j = i % 100;
            d_W1T[i] = W1[j*HH + k];
        }
        if (i < 100*50){
            int k = i / 50, j = i % 50;
            d_W2T[i] = W2[j*100 + k];
        }
        if (i < 4*HH) d_w0[i] = W_ih[(size_t)i*(HH+1)];
        return;
    }
    blk -= PREP_W_BLKS;
    if (blk < PREP_UA_BLKS){
        int idx = blk*256 + threadIdx.x;
        if (idx < NB*128){
            int n = idx >> 7, kq = idx & 127;
            int gk = kq*2;
            float2 v = make_float2(0.f, 0.f);
            if (n < HH && gk+1 < HH) v = *reinterpret_cast<const float2*>(Ua + (size_t)n*HH + gk);
            else if (n < HH && gk < HH) v.x = Ua[(size_t)n*HH + gk];
            uint32_t hi, lo; split2(v, hi, lo);
            d_UaHi[idx] = hi; d_UaLo[idx] = lo;
        }
        return;
    }
    blk -= PREP_UA_BLKS;
    {   // qproj: warp per (b,h)
        int w = blk*8 + (threadIdx.x>>5);
        int lane = threadIdx.x & 31;
        if (w >= BB*HH) return;
        int b = w / HH, h = w % HH;
        const float* q  = h0 + b*HH;
        const float* wa = Wa + (size_t)h*HH;
        float s = 0.f;
        #pragma unroll
        for (int k = lane; k < HH; k += 32) s += q[k]*wa[k];
        #pragma unroll
        for (int off = 16; off > 0; off >>= 1) s += __shfl_xor_sync(0xFFFFFFFFu, s, off);
        if (lane == 0) d_qpb[w] = s + ba[h] + bua[h];
    }
}

// ---- K2: register-prefetched A convert + double-buffered B cp.async + mma.sync
__global__ void __launch_bounds__(NTHR)
scores_mma_kernel(const float* __restrict__ enc,
                  const float* __restrict__ Va, const float* __restrict__ bva){
    extern __shared__ char sm[];
    uint32_t smb = smem_u32(sm);
    int tid  = threadIdx.x;
    int lane = tid & 31;
    int wid  = tid >> 5;
    int half = wid >> 3;
    int m0   = (wid & 7) * 16;
    int tile0 = half ? 13 : 0;
    int b  = blockIdx.y;
    int t0 = blockIdx.x * BM;

    float* qbS = (float*)(sm + OFF_QB);
    float* vaS = (float*)(sm + OFF_VA);
    float* red = (float*)(sm + OFF_RED);
    for (int h = tid; h < HH; h += NTHR){ qbS[h] = d_qpb[b*HH + h]; vaS[h] = Va[h]; }

    float c[13][4];
    #pragma unroll
    for (int i=0;i<13;i++){ c[i][0]=0.f; c[i][1]=0.f; c[i][2]=0.f; c[i][3]=0.f; }

    const float* encB = enc + ((size_t)(b*TT + t0))*HH;
    const uint4* uaHi4 = reinterpret_cast<const uint4*>(d_UaHi);
    const uint4* uaLo4 = reinterpret_cast<const uint4*>(d_UaLo);

    int aRow = m0 + (lane & 15);
    int aKof = ((lane >> 4) & 1) * 16;
    int bPairTileOff = (lane >> 4);
    int bPairKof  = ((lane >> 3) & 1) * 16;
    int bPairRow  = lane & 7;
    int bRowL = lane & 7;
    int bKofL = ((lane >> 3) & 1) * 16;

    int tA[8], kpA[8];
    #pragma unroll
    for (int r=0;r<8;r++){ int i = tid + r*NTHR; tA[r] = i>>5; kpA[r] = i&31; }

    // B prefetch helper: chunk ch into stage ch&1
    auto load_B = [&](int ch){
        uint32_t bh = smb + ((ch&1) ? OFF_B1H : OFF_B0H);
        uint32_t bl = smb + ((ch&1) ? OFF_B1L : OFF_B0L);
        int jmax = (ch < 3) ? 8 : 2;
        for (int i = tid; i < NB*jmax; i += NTHR){
            int n = i / jmax, j = i % jmax;
            cpa16(bh + n*SROW + j*16, uaHi4 + n*32 + ch*8 + j);
            cpa16(bl + n*SROW + j*16, uaLo4 + n*32 + ch*8 + j);
        }
        CP_COMMIT();
    };

    // prefetch chunk 0: A fp32 into regs, B into stage 0
    float2 cur[8], nxt[8];
    #pragma unroll
    for (int r=0;r<8;r++){
        int gk = kpA[r]*2;
        cur[r] = (gk+1 < HH) ? *reinterpret_cast<const float2*>(encB + (size_t)tA[r]*HH + gk)
                             : make_float2(0.f, 0.f);
    }
    load_B(0);

    #pragma unroll
    for (int ch = 0; ch < NCHUNK; ch++){
        __syncthreads();   // prev chunk's LDSMs done -> A smem reusable
        #pragma unroll
        for (int r=0;r<8;r++){
            uint32_t hi, lo; split2(cur[r], hi, lo);
            *(uint32_t*)(sm + OFF_AH + tA[r]*SROW + kpA[r]*4) = hi;
            *(uint32_t*)(sm + OFF_AL + tA[r]*SROW + kpA[r]*4) = lo;
        }
        CP_WAIT(0);        // B(ch) landed (drained during prev chunk's MMA)
        __syncthreads();

        // prefetch next chunk: B via cp.async (drains under MMA), A via LDG regs
        if (ch < NCHUNK-1){
            load_B(ch+1);
            #pragma unroll
            for (int r=0;r<8;r++){
                int gk = (ch+1)*KC + kpA[r]*2;
                nxt[r] = (gk+1 < HH) ? *reinterpret_cast<const float2*>(encB + (size_t)tA[r]*HH + gk)
                                     : make_float2(0.f, 0.f);
            }
        }

        uint32_t sbh = smb + ((ch&1) ? OFF_B1H : OFF_B0H);
        uint32_t sbl = smb + ((ch&1) ? OFF_B1L : OFF_B0L);
        int nkt = (ch < 3) ? 4 : 1;
        for (int ks = 0; ks < nkt; ks++){
            uint32_t aHi[4], aLo[4];
            uint32_t aoff = (uint32_t)(aRow*SROW + ks*32 + aKof);
            ldsm_x4(aHi, smb + OFF_AH + aoff);
            ldsm_x4(aLo, smb + OFF_AL + aoff);
            #pragma unroll
            for (int p = 0; p < 6; p++){
                uint32_t bHi[4], bLo[4];
                uint32_t boff = (uint32_t)((((tile0 + 2*p + bPairTileOff)*8) + bPairRow)*SROW
                                           + ks*32 + bPairKof);
                ldsm_x4(bHi, sbh + boff);
                ldsm_x4(bLo, sbl + boff);
                mma_bf16(c[2*p],   aHi, bHi);
                mma_bf16(c[2*p],   aHi, bLo);
                mma_bf16(c[2*p],   aLo, bHi);
                mma_bf16(c[2*p+1], aHi, bHi+2);
                mma_bf16(c[2*p+1], aHi, bLo+2);
                mma_bf16(c[2*p+1], aLo, bHi+2);
            }
            {
                uint32_t bHi[2], bLo[2];
                uint32_t boff = (uint32_t)(((tile0+12)*8 + bRowL)*SROW + ks*32 + bKofL);
                ldsm_x2(bHi, sbh + boff);
                ldsm_x2(bLo, sbl + boff);
                mma_bf16(c[12], aHi, bHi);
                mma_bf16(c[12], aHi, bLo);
                mma_bf16(c[12], aLo, bHi);
            }
        }
        #pragma unroll
        for (int r=0;r<8;r++) cur[r] = nxt[r];
    }

    float s0 = 0.f, s1 = 0.f;
    #pragma unroll
    for (int nt = 0; nt < 13; nt++){
        int h0 = (tile0+nt)*8 + (lane & 3)*2;
        if (h0 < HH){
            s0 += vaS[h0]  * fast_tanh(qbS[h0]  + c[nt][0]);
            s0 += vaS[h0+1]* fast_tanh(qbS[h0+1]+ c[nt][1]);
            s1 += vaS[h0]  * fast_tanh(qbS[h0]  + c[nt][2]);
            s1 += vaS[h0+1]* fast_tanh(qbS[h0+1]+ c[nt][3]);
        }
    }
    s0 += __shfl_xor_sync(0xFFFFFFFFu, s0, 1);
    s0 += __shfl_xor_sync(0xFFFFFFFFu, s0, 2);
    s1 += __shfl_xor_sync(0xFFFFFFFFu, s1, 1);
    s1 += __shfl_xor_sync(0xFFFFFFFFu, s1, 2);
    if ((lane & 3) == 0){
        int r0 = m0 + (lane >> 2);
        red[r0*2 + half]     = s0;
        red[(r0+8)*2 + half] = s1;
    }
    __syncthreads();
    if (tid < BM){
        d_scores[(size_t)b*TT + t0 + tid] = red[tid*2] + red[tid*2+1] + bva[0];
    }
}

// ------------------ K3: per-b softmax stats (max, 1/sum)
__global__ void softstat_kernel(){
    int b = blockIdx.x;
    int tid = threadIdx.x;
    __shared__ float red[256];
    float v[8];
    float m = -1e30f;
    #pragma unroll
    for (int i=0;i<8;i++){ v[i] = d_scores[(size_t)b*TT + tid + i*256]; m = fmaxf(m, v[i]); }
    red[tid] = m; __syncthreads();
    for (int s=128; s>0; s>>=1){ if (tid<s) red[tid]=fmaxf(red[tid],red[tid+s]); __syncthreads(); }
    m = red[0]; __syncthreads();
    float sum=0.f;
    #pragma unroll
    for (int i=0;i<8;i++) sum += __expf(v[i]-m);
    red[tid]=sum; __syncthreads();
    for (int s=128;s>0;s>>=1){ if(tid<s) red[tid]+=red[tid+s]; __syncthreads(); }
    if (tid==0){ d_smax[b] = m; d_sinv[b] = 1.0f/red[0]; }
}

// -------------------- K4: partial context, exp applied inline (grid BB x NSEG)
__global__ void context_part(const float* __restrict__ enc){
    int b = blockIdx.x, seg = blockIdx.y;
    const int TS = TT/NSEG;   // 64
    __shared__ float attnS[TS];
    int t00 = seg*TS;
    if (threadIdx.x < TS){
        float s = d_scores[(size_t)b*TT + t00 + threadIdx.x];
        attnS[threadIdx.x] = __expf(s - d_smax[b]) * d_sinv[b];
    }
    __syncthreads();
    int h = threadIdx.x;
    if (h < HH){
        const float* e = enc + (size_t)b*TT*HH + (size_t)t00*HH + h;
        float a0=0,a1=0,a2=0,a3=0,a4=0,a5=0,a6=0,a7=0;
        #pragma unroll
        for (int t=0;t<TS;t+=8){
            a0 += attnS[t]   * e[(size_t)t*HH];
            a1 += attnS[t+1] * e[(size_t)(t+1)*HH];
            a2 += attnS[t+2] * e[(size_t)(t+2)*HH];
            a3 += attnS[t+3] * e[(size_t)(t+3)*HH];
            a4 += attnS[t+4] * e[(size_t)(t+4)*HH];
            a5 += attnS[t+5] * e[(size_t)(t+5)*HH];
            a6 += attnS[t+6] * e[(size_t)(t+6)*HH];
            a7 += attnS[t+7] * e[(size_t)(t+7)*HH];
        }
        d_ctxp[(b*NSEG + seg)*HH + h] = ((a0+a1)+(a2+a3))+((a4+a5)+(a6+a7));
    }
}

// --------- K5: gate_base + decoder fused (800 threads)
__global__ void decoder_kernel(const float* __restrict__ x, const float* __restrict__ h0,
                               const float* __restrict__ c0,
                               const float* __restrict__ b_ih, const float* __restrict__ b_hh,
                               const float* __restrict__ b1,
                               const float* __restrict__ b2,
                               const float* __restrict__ W3, const float* __restrict__ b3,
                               float* __restrict__ out){
    int b = blockIdx.x;
    int tid = threadIdx.x;      // 0..799
    __shared__ float ctxS[HH], h0S[HH], c0S[HH];
    __shared__ float gb[4*HH], w0S[4*HH];
    __shared__ float hbuf[HH], o1[100], o2[50];
    __shared__ float xs;
    if (tid < HH){
        float s = 0.f;
        #pragma unroll
        for (int i=0;i<NSEG;i++) s += d_ctxp[(b*NSEG + i)*HH + tid];
        ctxS[tid] = s;
        h0S[tid] = h0[b*HH + tid];
        c0S[tid] = c0[b*HH + tid];
    }
    w0S[tid] = d_w0[tid];
    if (tid==0) xs = x[b];
    __syncthreads();
    {   // gate_base: one j per thread, coalesced WihT/WhhT
        int j = tid;
        float s = b_ih[j] + b_hh[j];
        #pragma unroll 4
        for (int k=0;k<HH;k++) s += ctxS[k]*d_WihT[k*4*HH + j] + h0S[k]*d_WhhT[k*4*HH + j];
        gb[j] = s;
    }
    __syncthreads();
    for (int st=0; st<STEPS; st++){
        float xv = xs;
        if (tid < HH){
            float ig = gb[tid]      + xv*w0S[tid];
            float fg = gb[HH+tid]   + xv*w0S[HH+tid];
            float gg = gb[2*HH+tid] + xv*w0S[2*HH+tid];
            float og = gb[3*HH+tid] + xv*w0S[3*HH+tid];
            float c  = sigm(fg)*c0S[tid] + sigm(ig)*fast_tanh(gg);
            float hn = sigm(og)*fast_tanh(c);
            hbuf[tid] = fmaxf(hn, 0.0f);
        }
        __syncthreads();
        if (tid < 100){
            float s1 = b1[tid];
            #pragma unroll 4
            for (int k=0;k<HH;k++) s1 += d_W1T[k*100 + tid]*hbuf[k];
            o1[tid] = fmaxf(s1, 0.0f);
        }
        __syncthreads();
        if (tid < 50){
            float s2 = b2[tid];
            #pragma unroll 4
            for (int k=0;k<100;k++) s2 += d_W2T[k*50 + tid]*o1[k];
            o2[tid] = fmaxf(s2, 0.0f);
        }
        __syncthreads();
        if (tid == 0){
            float y = b3[0];
            #pragma unroll
            for (int k=0;k<50;k++) y += W3[k]*o2[k];
            out[b*STEPS + st] = y;
            xs = y;
        }
        __syncthreads();
    }
}

extern "C" void kernel_launch(void* const* d_in, const int* in_sizes, int n_in,
                              void* d_out, int out_size){
    const float* x    = (const float*)d_in[0];
    const float* h0   = (const float*)d_in[1];
    const float* c0   = (const float*)d_in[2];
    const float* enc  = (const float*)d_in[3];
    const float* Wa   = (const float*)d_in[4];
    const float* ba   = (const float*)d_in[5];
    const float* Ua   = (const float*)d_in[6];
    const float* bua  = (const float*)d_in[7];
    const float* Va   = (const float*)d_in[8];
    const float* bva  = (const float*)d_in[9];
    const float* W_ih = (const float*)d_in[10];
    const float* W_hh = (const float*)d_in[11];
    const float* b_ih = (const float*)d_in[12];
    const float* b_hh = (const float*)d_in[13];
    const float* W1   = (const float*)d_in[14];
    const float* b1   = (const float*)d_in[15];
    const float* W2   = (const float*)d_in[16];
    const float* b2   = (const float*)d_in[17];
    const float* W3   = (const float*)d_in[18];
    const float* b3   = (const float*)d_in[19];
    float* out = (float*)d_out;

    static int smem_set = 0;
    if (!smem_set){
        cudaFuncSetAttribute(scores_mma_kernel,
                             cudaFuncAttributeMaxDynamicSharedMemorySize, SMEM_TOTAL);
        smem_set = 1;
    }

    prep_kernel<<<PREP_W_BLKS + PREP_UA_BLKS + PREP_Q_BLKS, 256>>>(
        Ua, W_ih, W_hh, W1, W2, h0, Wa, ba, bua);
    dim3 g2(TT/BM, BB);
    scores_mma_kernel<<<g2, NTHR, SMEM_TOTAL>>>(enc, Va, bva);
    softstat_kernel<<<BB, 256>>>();
    dim3 g4(BB, NSEG);
    context_part<<<g4, 256>>>(enc);
    decoder_kernel<<<BB, 4*HH>>>(x, h0, c0, b_ih, b_hh, b1, b2, W3, b3, out);
}

// round 16
// speedup vs baseline: 4.1018x; 1.1159x over previous
#include <cuda_runtime.h>
#include <cuda_bf16.h>
#include <cstdint>
#include <math.h>

#define BB 128
#define TT 2048
#define HH 200
#define STEPS 5

// ---------------- mma.sync scores-GEMM geometry (2 CTA/SM) ----------------
#define BM      64
#define KC      64
#define NCHUNK  4
#define NTHR    256
#define NB      208
#define SROW    144
// smem layout (single-buffered A and B)
#define OFF_AH   0
#define OFF_AL   9216
#define OFF_BH   18432
#define OFF_BL   48384
#define OFF_QB   78336
#define OFF_VA   79136
#define OFF_RED  79936
#define SMEM_TOTAL 80448

#define NSEG 64

__device__ float d_qpb[BB*HH];
__device__ float d_scores[BB*TT];
__device__ float d_smax[BB];
__device__ float d_sinv[BB];
__device__ float d_ctxp[BB*NSEG*HH];
__device__ uint32_t d_UaHi[NB*(KC*NCHUNK/2)];
__device__ uint32_t d_UaLo[NB*(KC*NCHUNK/2)];
__device__ float d_WihT[HH*4*HH];
__device__ float d_WhhT[HH*4*HH];
__device__ float d_W1T[HH*100];
__device__ float d_W2T[100*50];
__device__ float d_w0[4*HH];

__device__ __forceinline__ float fast_tanh(float x){
    float e = __expf(2.0f*x);
    return 1.0f - 2.0f/(e+1.0f);
}
__device__ __forceinline__ float sigm(float x){
    return 1.0f/(1.0f+__expf(-x));
}
__device__ __forceinline__ uint32_t smem_u32(const void* p){
    uint32_t a;
    asm("{ .reg .u64 t; cvta.to.shared.u64 t, %1; cvt.u32.u64 %0, t; }" : "=r"(a) : "l"(p));
    return a;
}
__device__ __forceinline__ void ldsm_x4(uint32_t* r, uint32_t addr){
    asm volatile("ldmatrix.sync.aligned.m8n8.x4.shared.b16 {%0,%1,%2,%3}, [%4];"
        : "=r"(r[0]),"=r"(r[1]),"=r"(r[2]),"=r"(r[3]) : "r"(addr));
}
__device__ __forceinline__ void ldsm_x2(uint32_t* r, uint32_t addr){
    asm volatile("ldmatrix.sync.aligned.m8n8.x2.shared.b16 {%0,%1}, [%2];"
        : "=r"(r[0]),"=r"(r[1]) : "r"(addr));
}
__device__ __forceinline__ void mma_bf16(float* c, const uint32_t* a, const uint32_t* b){
    asm volatile("mma.sync.aligned.m16n8k16.row.col.f32.bf16.bf16.f32 "
        "{%0,%1,%2,%3}, {%4,%5,%6,%7}, {%8,%9}, {%0,%1,%2,%3};"
        : "+f"(c[0]),"+f"(c[1]),"+f"(c[2]),"+f"(c[3])
        : "r"(a[0]),"r"(a[1]),"r"(a[2]),"r"(a[3]), "r"(b[0]),"r"(b[1]));
}
__device__ __forceinline__ void split1(float v, uint32_t& hi16, uint32_t& lo16){
    __nv_bfloat16 hb = __float2bfloat16_rn(v);
    __nv_bfloat16 lb = __float2bfloat16_rn(v - __bfloat162float(hb));
    hi16 = __bfloat16_as_ushort(hb);
    lo16 = __bfloat16_as_ushort(lb);
}
__device__ __forceinline__ void split2(float2 v, uint32_t& hi, uint32_t& lo){
    uint32_t h0,l0,h1,l1;
    split1(v.x,h0,l0); split1(v.y,h1,l1);
    hi = (h1<<16)|h0; lo = (l1<<16)|l0;
}
__device__ __forceinline__ void cpa16(uint32_t dst, const void* src){
    asm volatile("cp.async.ca.shared.global [%0], [%1], 16;" :: "r"(dst), "l"(src));
}
#define CP_COMMIT()  asm volatile("cp.async.commit_group;" ::: "memory")
#define CP_WAIT(n)   asm volatile("cp.async.wait_group %0;" :: "n"(n) : "memory")

// ---------------- K0 (merged prep): conv_w | conv_ua | qproj
#define PREP_W_BLKS   625
#define PREP_UA_BLKS  104
#define PREP_Q_BLKS   3200
__global__ void prep_kernel(const float* __restrict__ Ua,
                            const float* __restrict__ W_ih, const float* __restrict__ W_hh,
                            const float* __restrict__ W1, const float* __restrict__ W2,
                            const float* __restrict__ h0, const float* __restrict__ Wa,
                            const float* __restrict__ ba, const float* __restrict__ bua){
    int blk = blockIdx.x;
    if (blk < PREP_W_BLKS){
        int i = blk*256 + threadIdx.x;
        if (i < HH*4*HH){
            int k = i / (4*HH), j = i % (4*HH);
            d_WihT[i] = W_ih[(size_t)j*(HH+1) + 1 + k];
            d_WhhT[i] = W_hh[(size_t)j*HH + k];
        }
        if (i < HH*100){
            int k = i / 100, j = i % 100;
            d_W1T[i] = W1[j*HH + k];
        }
        if (i < 100*50){
            int k = i / 50, j = i % 50;
            d_W2T[i] = W2[j*100 + k];
        }
        if (i < 4*HH) d_w0[i] = W_ih[(size_t)i*(HH+1)];
        return;
    }
    blk -= PREP_W_BLKS;
    if (blk < PREP_UA_BLKS){
        int idx = blk*256 + threadIdx.x;
        if (idx < NB*128){
            int n = idx >> 7, kq = idx & 127;
            int gk = kq*2;
            float2 v = make_float2(0.f, 0.f);
            if (n < HH && gk+1 < HH) v = *reinterpret_cast<const float2*>(Ua + (size_t)n*HH + gk);
            else if (n < HH && gk < HH) v.x = Ua[(size_t)n*HH + gk];
            uint32_t hi, lo; split2(v, hi, lo);
            d_UaHi[idx] = hi; d_UaLo[idx] = lo;
        }
        return;
    }
    blk -= PREP_UA_BLKS;
    {   // qproj: warp per (b,h)
        int w = blk*8 + (threadIdx.x>>5);
        int lane = threadIdx.x & 31;
        if (w >= BB*HH) return;
        int b = w / HH, h = w % HH;
        const float* q  = h0 + b*HH;
        const float* wa = Wa + (size_t)h*HH;
        float s = 0.f;
        #pragma unroll
        for (int k = lane; k < HH; k += 32) s += q[k]*wa[k];
        #pragma unroll
        for (int off = 16; off > 0; off >>= 1) s += __shfl_xor_sync(0xFFFFFFFFu, s, off);
        if (lane == 0) d_qpb[w] = s + ba[h] + bua[h];
    }
}

// ---- K2: BM=64, 256 threads, 2 CTA/SM; reg-prefetched A convert + mma.sync
__global__ void __launch_bounds__(NTHR, 2)
scores_mma_kernel(const float* __restrict__ enc,
                  const float* __restrict__ Va, const float* __restrict__ bva){
    extern __shared__ char sm[];
    uint32_t smb = smem_u32(sm);
    int tid  = threadIdx.x;
    int lane = tid & 31;
    int wid  = tid >> 5;              // 0..7
    int half = wid >> 2;              // 0/1: n-tiles 0..12 / 13..25
    int m0   = (wid & 3) * 16;        // 4 m-strips of 16 rows
    int tile0 = half ? 13 : 0;
    int b  = blockIdx.y;
    int t0 = blockIdx.x * BM;

    float* qbS = (float*)(sm + OFF_QB);
    float* vaS = (float*)(sm + OFF_VA);
    float* red = (float*)(sm + OFF_RED);
    for (int h = tid; h < HH; h += NTHR){ qbS[h] = d_qpb[b*HH + h]; vaS[h] = Va[h]; }

    float c[13][4];
    #pragma unroll
    for (int i=0;i<13;i++){ c[i][0]=0.f; c[i][1]=0.f; c[i][2]=0.f; c[i][3]=0.f; }

    const float* encB = enc + ((size_t)(b*TT + t0))*HH;
    const uint4* uaHi4 = reinterpret_cast<const uint4*>(d_UaHi);
    const uint4* uaLo4 = reinterpret_cast<const uint4*>(d_UaLo);

    int aRow = m0 + (lane & 15);
    int aKof = ((lane >> 4) & 1) * 16;
    int bPairTileOff = (lane >> 4);
    int bPairKof  = ((lane >> 3) & 1) * 16;
    int bPairRow  = lane & 7;
    int bRowL = lane & 7;
    int bKofL = ((lane >> 3) & 1) * 16;

    // per-thread A mapping: i = tid + r*NTHR over BM*32 = 2048 pairs
    int tA[8], kpA[8];
    #pragma unroll
    for (int r=0;r<8;r++){ int i = tid + r*NTHR; tA[r] = i>>5; kpA[r] = i&31; }

    float2 cur[8], nxt[8];
    #pragma unroll
    for (int r=0;r<8;r++){
        int gk = kpA[r]*2;
        cur[r] = (gk+1 < HH) ? *reinterpret_cast<const float2*>(encB + (size_t)tA[r]*HH + gk)
                             : make_float2(0.f, 0.f);
    }

    #pragma unroll
    for (int ch = 0; ch < NCHUNK; ch++){
        __syncthreads();   // prev chunk's LDSMs done -> smem reusable
        // B: issue cp.async first (drains while we do the A STS work)
        {
            int jmax = (ch < 3) ? 8 : 2;
            for (int i = tid; i < NB*jmax; i += NTHR){
                int n = i / jmax, j = i % jmax;
                cpa16(smb + OFF_BH + n*SROW + j*16, uaHi4 + n*32 + ch*8 + j);
                cpa16(smb + OFF_BL + n*SROW + j*16, uaLo4 + n*32 + ch*8 + j);
            }
            CP_COMMIT();
        }
        // A: convert prefetched regs -> smem
        #pragma unroll
        for (int r=0;r<8;r++){
            uint32_t hi, lo; split2(cur[r], hi, lo);
            *(uint32_t*)(sm + OFF_AH + tA[r]*SROW + kpA[r]*4) = hi;
            *(uint32_t*)(sm + OFF_AL + tA[r]*SROW + kpA[r]*4) = lo;
        }
        CP_WAIT(0);
        __syncthreads();

        // prefetch next chunk's A (LDGs drain under MMA below)
        if (ch < NCHUNK-1){
            #pragma unroll
            for (int r=0;r<8;r++){
                int gk = (ch+1)*KC + kpA[r]*2;
                nxt[r] = (gk+1 < HH) ? *reinterpret_cast<const float2*>(encB + (size_t)tA[r]*HH + gk)
                                     : make_float2(0.f, 0.f);
            }
        }

        int nkt = (ch < 3) ? 4 : 1;
        for (int ks = 0; ks < nkt; ks++){
            uint32_t aHi[4], aLo[4];
            uint32_t aoff = (uint32_t)(aRow*SROW + ks*32 + aKof);
            ldsm_x4(aHi, smb + OFF_AH + aoff);
            ldsm_x4(aLo, smb + OFF_AL + aoff);
            #pragma unroll
            for (int p = 0; p < 6; p++){
                uint32_t bHi[4], bLo[4];
                uint32_t boff = (uint32_t)((((tile0 + 2*p + bPairTileOff)*8) + bPairRow)*SROW
                                           + ks*32 + bPairKof);
                ldsm_x4(bHi, smb + OFF_BH + boff);
                ldsm_x4(bLo, smb + OFF_BL + boff);
                mma_bf16(c[2*p],   aHi, bHi);
                mma_bf16(c[2*p],   aHi, bLo);
                mma_bf16(c[2*p],   aLo, bHi);
                mma_bf16(c[2*p+1], aHi, bHi+2);
                mma_bf16(c[2*p+1], aHi, bLo+2);
                mma_bf16(c[2*p+1], aLo, bHi+2);
            }
            {
                uint32_t bHi[2], bLo[2];
                uint32_t boff = (uint32_t)(((tile0+12)*8 + bRowL)*SROW + ks*32 + bKofL);
                ldsm_x2(bHi, smb + OFF_BH + boff);
                ldsm_x2(bLo, smb + OFF_BL + boff);
                mma_bf16(c[12], aHi, bHi);
                mma_bf16(c[12], aHi, bLo);
                mma_bf16(c[12], aLo, bHi);
            }
        }
        #pragma unroll
        for (int r=0;r<8;r++) cur[r] = nxt[r];
    }

    float s0 = 0.f, s1 = 0.f;
    #pragma unroll
    for (int nt = 0; nt < 13; nt++){
        int h0 = (tile0+nt)*8 + (lane & 3)*2;
        if (h0 < HH){
            s0 += vaS[h0]  * fast_tanh(qbS[h0]  + c[nt][0]);
            s0 += vaS[h0+1]* fast_tanh(qbS[h0+1]+ c[nt][1]);
            s1 += vaS[h0]  * fast_tanh(qbS[h0]  + c[nt][2]);
            s1 += vaS[h0+1]* fast_tanh(qbS[h0+1]+ c[nt][3]);
        }
    }
    s0 += __shfl_xor_sync(0xFFFFFFFFu, s0, 1);
    s0 += __shfl_xor_sync(0xFFFFFFFFu, s0, 2);
    s1 += __shfl_xor_sync(0xFFFFFFFFu, s1, 1);
    s1 += __shfl_xor_sync(0xFFFFFFFFu, s1, 2);
    if ((lane & 3) == 0){
        int r0 = m0 + (lane >> 2);
        red[r0*2 + half]     = s0;
        red[(r0+8)*2 + half] = s1;
    }
    __syncthreads();
    if (tid < BM){
        d_scores[(size_t)b*TT + t0 + tid] = red[tid*2] + red[tid*2+1] + bva[0];
    }
}

// ------------------ K3: per-b softmax stats (max, 1/sum)
__global__ void softstat_kernel(){
    int b = blockIdx.x;
    int tid = threadIdx.x;
    __shared__ float red[256];
    float v[8];
    float m = -1e30f;
    #pragma unroll
    for (int i=0;i<8;i++){ v[i] = d_scores[(size_t)b*TT + tid + i*256]; m = fmaxf(m, v[i]); }
    red[tid] = m; __syncthreads();
    for (int s=128; s>0; s>>=1){ if (tid<s) red[tid]=fmaxf(red[tid],red[tid+s]); __syncthreads(); }
    m = red[0]; __syncthreads();
    float sum=0.f;
    #pragma unroll
    for (int i=0;i<8;i++) sum += __expf(v[i]-m);
    red[tid]=sum; __syncthreads();
    for (int s=128;s>0;s>>=1){ if(tid<s) red[tid]+=red[tid+s]; __syncthreads(); }
    if (tid==0){ d_smax[b] = m; d_sinv[b] = 1.0f/red[0]; }
}

// -------------------- K4: partial context, exp inline (grid BB x NSEG)
__global__ void context_part(const float* __restrict__ enc){
    int b = blockIdx.x, seg = blockIdx.y;
    const int TS = TT/NSEG;   // 32
    __shared__ float attnS[TS];
    int t00 = seg*TS;
    if (threadIdx.x < TS){
        float s = d_scores[(size_t)b*TT + t00 + threadIdx.x];
        attnS[threadIdx.x] = __expf(s - d_smax[b]) * d_sinv[b];
    }
    __syncthreads();
    int h = threadIdx.x;
    if (h < HH){
        const float* e = enc + (size_t)b*TT*HH + (size_t)t00*HH + h;
        float a0=0,a1=0,a2=0,a3=0,a4=0,a5=0,a6=0,a7=0;
        #pragma unroll
        for (int t=0;t<TS;t+=8){
            a0 += attnS[t]   * e[(size_t)t*HH];
            a1 += attnS[t+1] * e[(size_t)(t+1)*HH];
            a2 += attnS[t+2] * e[(size_t)(t+2)*HH];
            a3 += attnS[t+3] * e[(size_t)(t+3)*HH];
            a4 += attnS[t+4] * e[(size_t)(t+4)*HH];
            a5 += attnS[t+5] * e[(size_t)(t+5)*HH];
            a6 += attnS[t+6] * e[(size_t)(t+6)*HH];
            a7 += attnS[t+7] * e[(size_t)(t+7)*HH];
        }
        d_ctxp[(b*NSEG + seg)*HH + h] = ((a0+a1)+(a2+a3))+((a4+a5)+(a6+a7));
    }
}

// --------- K5: gate_base + decoder fused (800 threads)
__global__ void decoder_kernel(const float* __restrict__ x, const float* __restrict__ h0,
                               const float* __restrict__ c0,
                               const float* __restrict__ b_ih, const float* __restrict__ b_hh,
                               const float* __restrict__ b1,
                               const float* __restrict__ b2,
                               const float* __restrict__ W3, const float* __restrict__ b3,
                               float* __restrict__ out){
    int b = blockIdx.x;
    int tid = threadIdx.x;      // 0..799
    __shared__ float ctxS[HH], h0S[HH], c0S[HH];
    __shared__ float gb[4*HH], w0S[4*HH];
    __shared__ float hbuf[HH], o1[100], o2[50];
    __shared__ float xs;
    if (tid < HH){
        float s = 0.f;
        #pragma unroll
        for (int i=0;i<NSEG;i++) s += d_ctxp[(b*NSEG + i)*HH + tid];
        ctxS[tid] = s;
        h0S[tid] = h0[b*HH + tid];
        c0S[tid] = c0[b*HH + tid];
    }
    w0S[tid] = d_w0[tid];
    if (tid==0) xs = x[b];
    __syncthreads();
    {
        int j = tid;
        float s = b_ih[j] + b_hh[j];
        #pragma unroll 4
        for (int k=0;k<HH;k++) s += ctxS[k]*d_WihT[k*4*HH + j] + h0S[k]*d_WhhT[k*4*HH + j];
        gb[j] = s;
    }
    __syncthreads();
    for (int st=0; st<STEPS; st++){
        float xv = xs;
        if (tid < HH){
            float ig = gb[tid]      + xv*w0S[tid];
            float fg = gb[HH+tid]   + xv*w0S[HH+tid];
            float gg = gb[2*HH+tid] + xv*w0S[2*HH+tid];
            float og = gb[3*HH+tid] + xv*w0S[3*HH+tid];
            float c  = sigm(fg)*c0S[tid] + sigm(ig)*fast_tanh(gg);
            float hn = sigm(og)*fast_tanh(c);
            hbuf[tid] = fmaxf(hn, 0.0f);
        }
        __syncthreads();
        if (tid < 100){
            float s1 = b1[tid];
            #pragma unroll 4
            for (int k=0;k<HH;k++) s1 += d_W1T[k*100 + tid]*hbuf[k];
            o1[tid] = fmaxf(s1, 0.0f);
        }
        __syncthreads();
        if (tid < 50){
            float s2 = b2[tid];
            #pragma unroll 4
            for (int k=0;k<100;k++) s2 += d_W2T[k*50 + tid]*o1[k];
            o2[tid] = fmaxf(s2, 0.0f);
        }
        __syncthreads();
        if (tid == 0){
            float y = b3[0];
            #pragma unroll
            for (int k=0;k<50;k++) y += W3[k]*o2[k];
            out[b*STEPS + st] = y;
            xs = y;
        }
        __syncthreads();
    }
}

extern "C" void kernel_launch(void* const* d_in, const int* in_sizes, int n_in,
                              void* d_out, int out_size){
    const float* x    = (const float*)d_in[0];
    const float* h0   = (const float*)d_in[1];
    const float* c0   = (const float*)d_in[2];
    const float* enc  = (const float*)d_in[3];
    const float* Wa   = (const float*)d_in[4];
    const float* ba   = (const float*)d_in[5];
    const float* Ua   = (const float*)d_in[6];
    const float* bua  = (const float*)d_in[7];
    const float* Va   = (const float*)d_in[8];
    const float* bva  = (const float*)d_in[9];
    const float* W_ih = (const float*)d_in[10];
    const float* W_hh = (const float*)d_in[11];
    const float* b_ih = (const float*)d_in[12];
    const float* b_hh = (const float*)d_in[13];
    const float* W1   = (const float*)d_in[14];
    const float* b1   = (const float*)d_in[15];
    const float* W2   = (const float*)d_in[16];
    const float* b2   = (const float*)d_in[17];
    const float* W3   = (const float*)d_in[18];
    const float* b3   = (const float*)d_in[19];
    float* out = (float*)d_out;

    static int smem_set = 0;
    if (!smem_set){
        cudaFuncSetAttribute(scores_mma_kernel,
                             cudaFuncAttributeMaxDynamicSharedMemorySize, SMEM_TOTAL);
        smem_set = 1;
    }

    prep_kernel<<<PREP_W_BLKS + PREP_UA_BLKS + PREP_Q_BLKS, 256>>>(
        Ua, W_ih, W_hh, W1, W2, h0, Wa, ba, bua);
    dim3 g2(TT/BM, BB);
    scores_mma_kernel<<<g2, NTHR, SMEM_TOTAL>>>(enc, Va, bva);
    softstat_kernel<<<BB, 256>>>();
    dim3 g4(BB, NSEG);
    context_part<<<g4, 256>>>(enc);
    decoder_kernel<<<BB, 4*HH>>>(x, h0, c0, b_ih, b_hh, b1, b2, W3, b3, out);
}